// round 12
// baseline (speedup 1.0000x reference)
#include <cuda_runtime.h>
#include <math.h>

// ---------------- constants ----------------
constexpr int cB = 32, cN = 32, cE = 64, cW = 40, cHgrid = 40, cHW = 1600;
constexpr int cD = 256, cNH = 8, cDH = 32, cL = 6;
constexpr int cTn = cB * cN;          // 1024
constexpr int cTe = cB * cE;          // 2048
constexpr int cT  = cTn + cTe;        // 3072
constexpr int cTB = cN + cE;          // 96 tokens per batch
constexpr int cFF = 1024;
constexpr int cFKV = cB * cHW;        // 51200
constexpr int SPLITS = 8;
constexpr int KSPLIT = cHW / SPLITS;  // 200
constexpr int KTILE = 64;
constexpr float ATTN_SCALE = 0.17677669529663689f; // 1/sqrt(32)
constexpr float LOG1E4 = 9.210340371976184f;

// ---------------- scratch arena ----------------
constexpr size_t SZ_TD = (size_t)cT * cD;           // 786432
constexpr size_t O_Q    = 0;
constexpr size_t O_X    = O_Q    + SZ_TD;
constexpr size_t O_XE   = O_X    + SZ_TD;
constexpr size_t O_TMP  = O_XE   + SZ_TD;
constexpr size_t O_QH   = O_TMP  + SZ_TD;
constexpr size_t O_AO   = O_QH   + SZ_TD;
constexpr size_t O_EMB  = O_AO   + SZ_TD;
constexpr size_t O_BIAS = O_EMB  + SZ_TD;                       // cT*cHW
constexpr size_t O_KH   = O_BIAS + (size_t)cT * cHW;            // cFKV*512 (packed K|V)
constexpr size_t O_Y1   = O_KH   + (size_t)cFKV * 512;          // cT*cFF
constexpr size_t O_HN   = O_Y1   + (size_t)cT * cFF;            // cTn*cD
constexpr size_t O_EE   = O_HN   + (size_t)cTn * cD;            // cTe*cD
constexpr size_t O_NAGG = O_EE   + (size_t)cTe * cD;            // cTn*cD
constexpr size_t O_PM   = O_NAGG + (size_t)cTn * cD;            // B*NH*TB*SPLITS
constexpr size_t SZ_P   = (size_t)cB * cNH * cTB * SPLITS;      // 196608
constexpr size_t O_PDEN = O_PM   + SZ_P;
constexpr size_t O_PACC = O_PDEN + SZ_P;                        // SZ_P*cDH
constexpr size_t O_TOTAL = O_PACC + SZ_P * cDH;

__device__ __align__(16) float g_buf[O_TOTAL];
__device__ int   g_src[cTe];
__device__ int   g_dst[cTe];
__device__ int   g_cnt[cTn];
__device__ int   g_list[cTn * 64];
__device__ float g_As[cTn * cNH];
__device__ float g_Ad[cTn * cNH];
__device__ float g_Ae[cTe * cNH];

// ---------------- helpers ----------------
__device__ __forceinline__ int row_of(int b, int t) {
    return (t < cN) ? b * cN + t : cTn + b * cE + (t - cN);
}

__device__ __forceinline__ void mma8(float* c, const unsigned* a, const unsigned* b) {
    asm volatile(
        "mma.sync.aligned.m16n8k8.row.col.f32.tf32.tf32.f32 "
        "{%0,%1,%2,%3}, {%4,%5,%6,%7}, {%8,%9}, {%0,%1,%2,%3};"
        : "+f"(c[0]), "+f"(c[1]), "+f"(c[2]), "+f"(c[3])
        : "r"(a[0]), "r"(a[1]), "r"(a[2]), "r"(a[3]), "r"(b[0]), "r"(b[1]));
}

__device__ __forceinline__ void cpasync16(unsigned sa, const void* g) {
    asm volatile("cp.async.cg.shared.global [%0], [%1], 16;\n" :: "r"(sa), "l"(g));
}
__device__ __forceinline__ void cpcommit() { asm volatile("cp.async.commit_group;\n"); }
template <int W> __device__ __forceinline__ void cpwait() {
    asm volatile("cp.async.wait_group %0;\n" :: "n"(W));
}

__device__ __forceinline__ unsigned long long ffma2(unsigned long long a,
                                                    unsigned long long b,
                                                    unsigned long long c) {
    unsigned long long d;
    asm("fma.rn.f32x2 %0, %1, %2, %3;" : "=l"(d) : "l"(a), "l"(b), "l"(c));
    return d;
}
__device__ __forceinline__ unsigned long long pack2(float lo, float hi) {
    unsigned long long d;
    asm("mov.b64 %0, {%1, %2};" : "=l"(d) : "f"(lo), "f"(hi));
    return d;
}
__device__ __forceinline__ float2 unpack2(unsigned long long v) {
    float lo, hi;
    asm("mov.b64 {%0, %1}, %2;" : "=f"(lo), "=f"(hi) : "l"(v));
    return make_float2(lo, hi);
}

// ---------------- precompute kernels ----------------
__global__ void k_edges(const int* __restrict__ el) {
    int e = blockIdx.x * blockDim.x + threadIdx.x;
    if (e < cTe) {
        int b = e / cE;
        g_src[e] = el[e] + b * cN;
        g_dst[e] = el[cTe + e] + b * cN;
    }
    if (e < cTn) g_cnt[e] = 0;
}

__global__ void k_csr() {
    int e = blockIdx.x * blockDim.x + threadIdx.x;
    if (e < cTe) {
        int d = g_dst[e];
        int slot = atomicAdd(&g_cnt[d], 1);
        g_list[d * 64 + slot] = e;
    }
}

__global__ void k_node_heat(const float* __restrict__ boxes) {
    int nd = blockIdx.x;
    int t = threadIdx.x;
    __shared__ float hx[cW], hy[cHgrid];
    float cx = boxes[nd * 4 + 0], cy = boxes[nd * 4 + 1];
    float w  = boxes[nd * 4 + 2], h  = boxes[nd * 4 + 3];
    if (t < cW) {
        float gx = (t + 0.5f) / cW;
        float dd = gx - cx;
        hx[t] = expf(-dd * dd / (0.5f * w * w + 1e-6f));
    } else if (t < cW + cHgrid) {
        int y = t - cW;
        float gy = (y + 0.5f) / cHgrid;
        float dd = gy - cy;
        hy[y] = expf(-dd * dd / (0.5f * h * h + 1e-6f));
    }
    __syncthreads();
    float* out = g_buf + O_BIAS + (size_t)nd * cHW;
    for (int i = t; i < cHW; i += blockDim.x)
        out[i] = hy[i / cW] * hx[i % cW];
}

__global__ void k_edge_heat(const float* __restrict__ boxes) {
    int e = blockIdx.x;
    int t = threadIdx.x;
    int s = g_src[e], d = g_dst[e];
    float c1x = boxes[s*4+0], c1y = boxes[s*4+1], w1 = boxes[s*4+2], h1 = boxes[s*4+3];
    float c2x = boxes[d*4+0], c2y = boxes[d*4+1], w2 = boxes[d*4+2], h2 = boxes[d*4+3];
    float ux1 = fminf(c1x - w1*0.5f, c2x - w2*0.5f);
    float uy1 = fminf(c1y - h1*0.5f, c2y - h2*0.5f);
    float ux2 = fmaxf(c1x + w1*0.5f, c2x + w2*0.5f);
    float uy2 = fmaxf(c1y + h1*0.5f, c2y + h2*0.5f);
    float ucx = (ux1 + ux2) * 0.5f, ucy = (uy1 + uy2) * 0.5f;
    float uw = ux2 - ux1, uh = uy2 - uy1;
    __shared__ float hx[cW], hy[cHgrid];
    if (t < cW) {
        float gx = (t + 0.5f) / cW;
        float dd = gx - ucx;
        hx[t] = expf(-dd * dd / (0.5f * uw * uw + 1e-6f));
    } else if (t < cW + cHgrid) {
        int y = t - cW;
        float gy = (y + 0.5f) / cHgrid;
        float dd = gy - ucy;
        hy[y] = expf(-dd * dd / (0.5f * uh * uh + 1e-6f));
    }
    __syncthreads();
    const float* hs = g_buf + O_BIAS + (size_t)s * cHW;
    const float* hd = g_buf + O_BIAS + (size_t)d * cHW;
    float* out = g_buf + O_BIAS + (size_t)(cTn + e) * cHW;
    for (int i = t; i < cHW; i += blockDim.x) {
        float u = hy[i / cW] * hx[i % cW];
        out[i] = fmaxf(fmaxf(hs[i], hd[i]), u);
    }
}

// emb + initial Q fill (nodes0|edges0)
__global__ void k_emb(const float* __restrict__ boxes, const float* __restrict__ nodes0,
                      const float* __restrict__ edges0) {
    int i = blockIdx.x * blockDim.x + threadIdx.x;
    if (i >= cT * cD) return;
    int r = i / cD, ch = i % cD;
    int c = ch >> 6;
    int j = ch & 63;
    int fj = j & 31;
    float v;
    if (r < cTn) {
        v = boxes[r * 4 + c];
        g_buf[O_Q + i] = nodes0[i];
    } else {
        int e = r - cTn;
        v = boxes[g_src[e] * 4 + c] - boxes[g_dst[e] * 4 + c];
        g_buf[O_Q + i] = edges0[i - cTn * cD];
    }
    float fr = expf(-LOG1E4 * (float)fj / 32.0f);
    float ang = v * fr;
    g_buf[O_EMB + i] = (j < 32) ? sinf(ang) : cosf(ang);
}

// LayerNorm: warp per row, 8 rows/block; optional xe = out + emb second output.
__global__ void __launch_bounds__(256) k_ln(const float* __restrict__ in,
                                            const float* __restrict__ gg,
                                            const float* __restrict__ bt,
                                            float* __restrict__ out,
                                            float* __restrict__ xe,
                                            const float* __restrict__ emb) {
    int warp = threadIdx.x >> 5, lane = threadIdx.x & 31;
    size_t r = (size_t)blockIdx.x * 8 + warp;
    const float4* row = (const float4*)(in + r * cD);
    float4 v0 = row[lane * 2], v1 = row[lane * 2 + 1];
    float s = v0.x + v0.y + v0.z + v0.w + v1.x + v1.y + v1.z + v1.w;
    #pragma unroll
    for (int o = 16; o; o >>= 1) s += __shfl_xor_sync(0xffffffffu, s, o);
    float mean = s * (1.0f / cD);
    v0.x -= mean; v0.y -= mean; v0.z -= mean; v0.w -= mean;
    v1.x -= mean; v1.y -= mean; v1.z -= mean; v1.w -= mean;
    float s2 = v0.x*v0.x + v0.y*v0.y + v0.z*v0.z + v0.w*v0.w
             + v1.x*v1.x + v1.y*v1.y + v1.z*v1.z + v1.w*v1.w;
    #pragma unroll
    for (int o = 16; o; o >>= 1) s2 += __shfl_xor_sync(0xffffffffu, s2, o);
    float inv = rsqrtf(s2 * (1.0f / cD) + 1e-5f);
    const float4* g4 = (const float4*)gg;
    const float4* b4 = (const float4*)bt;
    float4 ga = g4[lane * 2], gb = g4[lane * 2 + 1];
    float4 ba = b4[lane * 2], bb = b4[lane * 2 + 1];
    float4 o0, o1;
    o0.x = v0.x * inv * ga.x + ba.x; o0.y = v0.y * inv * ga.y + ba.y;
    o0.z = v0.z * inv * ga.z + ba.z; o0.w = v0.w * inv * ga.w + ba.w;
    o1.x = v1.x * inv * gb.x + bb.x; o1.y = v1.y * inv * gb.y + bb.y;
    o1.z = v1.z * inv * gb.z + bb.z; o1.w = v1.w * inv * gb.w + bb.w;
    float4* po = (float4*)(out + r * cD);
    po[lane * 2] = o0; po[lane * 2 + 1] = o1;
    if (xe) {
        const float4* e4 = (const float4*)(emb + r * cD);
        float4 e0 = e4[lane * 2], e1 = e4[lane * 2 + 1];
        float4 x0, x1;
        x0.x = o0.x + e0.x; x0.y = o0.y + e0.y; x0.z = o0.z + e0.z; x0.w = o0.w + e0.w;
        x1.x = o1.x + e1.x; x1.y = o1.y + e1.y; x1.z = o1.z + e1.z; x1.w = o1.w + e1.w;
        float4* px = (float4*)(xe + r * cD);
        px[lane * 2] = x0; px[lane * 2 + 1] = x1;
    }
}

// ---------------- tf32 tensor-core GEMM, 128x128x16, cp.async double-buffered ----
// C[M,N] = A[M,K] * op(B); TB: B is [N,K] (op=B^T); !TB: B is [K,N].
// EPI: 0=none, 1=+bias, 2=+bias,gelu, 3: C += ls*(v+bias) (opt dual store D2),
//      4: C = X + ls*(v+bias)
// 256 threads = 8 warps (2M x 4N), warp tile 64x32. Requires M%128==0, N%128==0.
template <bool TB, int EPI>
__global__ void __launch_bounds__(256) k_mma(const float* __restrict__ A,
                                             const float* __restrict__ Bw,
                                             const float* __restrict__ bias,
                                             float* __restrict__ C,
                                             const float* __restrict__ X,
                                             const float* __restrict__ ls,
                                             float* __restrict__ D2,
                                             int M, int N, int K) {
    constexpr int BR = TB ? 128 : 16;
    constexpr int BC = TB ? 20 : 132;
    __shared__ float As[2][128][20];
    __shared__ float Bs[2][BR][BC];
    const int tid = threadIdx.x;
    const int m0 = blockIdx.y * 128, n0 = blockIdx.x * 128;
    const int wid = tid >> 5, lane = tid & 31;
    const int wm = (wid & 1) * 64, wn = (wid >> 1) * 32;
    const int g = lane >> 2, tg = lane & 3;
    float c[4][4][4] = {};

    auto loadA = [&](int st, int k0) {
        #pragma unroll
        for (int h = 0; h < 2; h++) {
            int idx = tid + h * 256;
            int row = idx >> 2, c4 = idx & 3;
            unsigned sa = (unsigned)__cvta_generic_to_shared(&As[st][row][c4 * 4]);
            cpasync16(sa, A + (size_t)(m0 + row) * K + k0 + c4 * 4);
        }
    };
    auto loadB = [&](int st, int k0) {
        if constexpr (TB) {
            #pragma unroll
            for (int h = 0; h < 2; h++) {
                int idx = tid + h * 256;
                int row = idx >> 2, c4 = idx & 3;
                unsigned sa = (unsigned)__cvta_generic_to_shared(&Bs[st][row][c4 * 4]);
                cpasync16(sa, Bw + (size_t)(n0 + row) * K + k0 + c4 * 4);
            }
        } else {
            #pragma unroll
            for (int h = 0; h < 2; h++) {
                int idx = tid + h * 256;
                int row = idx >> 5, c4 = idx & 31;
                unsigned sa = (unsigned)__cvta_generic_to_shared(&Bs[st][row][c4 * 4]);
                cpasync16(sa, Bw + (size_t)(k0 + row) * N + n0 + c4 * 4);
            }
        }
    };

    const int T = K >> 4;
    loadA(0, 0); loadB(0, 0); cpcommit();
    for (int it = 0; it < T; it++) {
        int st = it & 1;
        if (it + 1 < T) {
            loadA(st ^ 1, (it + 1) * 16);
            loadB(st ^ 1, (it + 1) * 16);
            cpcommit();
            cpwait<1>();
        } else {
            cpwait<0>();
        }
        __syncthreads();
        #pragma unroll
        for (int kk = 0; kk < 16; kk += 8) {
            unsigned a[4][4], b[4][2];
            #pragma unroll
            for (int i = 0; i < 4; i++) {
                int m = wm + i * 16 + g;
                a[i][0] = __float_as_uint(As[st][m][kk + tg]);
                a[i][1] = __float_as_uint(As[st][m + 8][kk + tg]);
                a[i][2] = __float_as_uint(As[st][m][kk + tg + 4]);
                a[i][3] = __float_as_uint(As[st][m + 8][kk + tg + 4]);
            }
            #pragma unroll
            for (int j = 0; j < 4; j++) {
                int n = wn + j * 8 + g;
                if constexpr (TB) {
                    b[j][0] = __float_as_uint(Bs[st][n][kk + tg]);
                    b[j][1] = __float_as_uint(Bs[st][n][kk + tg + 4]);
                } else {
                    b[j][0] = __float_as_uint(Bs[st][kk + tg][n]);
                    b[j][1] = __float_as_uint(Bs[st][kk + tg + 4][n]);
                }
            }
            #pragma unroll
            for (int i = 0; i < 4; i++)
                #pragma unroll
                for (int j = 0; j < 4; j++)
                    mma8(c[i][j], a[i], b[j]);
        }
        __syncthreads();
    }
    #pragma unroll
    for (int i = 0; i < 4; i++) {
        #pragma unroll
        for (int j = 0; j < 4; j++) {
            int col = n0 + wn + j * 8 + tg * 2;
            #pragma unroll
            for (int p = 0; p < 4; p++) {
                int row = m0 + wm + i * 16 + g + ((p >= 2) ? 8 : 0);
                int cc = col + (p & 1);
                float v = c[i][j][p];
                if (EPI >= 1) v += bias[cc];
                if (EPI == 2) v = 0.5f * v * (1.0f + erff(v * 0.70710678118654752f));
                size_t idx = (size_t)row * N + cc;
                if (EPI == 3) {
                    float nv = C[idx] + ls[cc] * v;
                    C[idx] = nv;
                    if (D2) D2[idx] = nv;
                } else if (EPI == 4) {
                    C[idx] = X[idx] + ls[cc] * v;
                } else {
                    C[idx] = v;
                }
            }
        }
    }
}

// ---------------- attention (flash-style, key-split, f32x2 packed) ----------------
// K/V packed: row stride 512 floats, K at +0, V at +256
__global__ void __launch_bounds__(96) k_attn_partial() {
    int h = blockIdx.x, b = blockIdx.y, s = blockIdx.z;
    int q = threadIdx.x; // 0..95
    __shared__ __align__(16) float ks[KTILE][32];
    __shared__ __align__(16) float vs[KTILE][32];
    const float* khv = g_buf + O_KH;
    int r = row_of(b, q);
    unsigned long long q2[16];
    {
        const float2* qp = (const float2*)(g_buf + O_QH + (size_t)r * cD + h * cDH);
        #pragma unroll
        for (int d = 0; d < 16; d++) { float2 t = qp[d]; q2[d] = pack2(t.x, t.y); }
    }
    const float* brow = g_buf + O_BIAS + (size_t)r * cHW;
    float m = -INFINITY, den = 0.f;
    unsigned long long acc[16];
    #pragma unroll
    for (int d = 0; d < 16; d++) acc[d] = 0ull;
    int kbeg = s * KSPLIT;
    for (int k0 = kbeg; k0 < kbeg + KSPLIT; k0 += KTILE) {
        int kt = min(KTILE, kbeg + KSPLIT - k0);
        __syncthreads();
        for (int idx = q; idx < kt * 8; idx += 96) {
            int kk = idx >> 3, d4 = idx & 7;
            const float4* src = (const float4*)(khv + (size_t)(b * cHW + k0 + kk) * 512
                                                + h * cDH + d4 * 4);
            *(float4*)&ks[kk][d4 * 4] = src[0];
            *(float4*)&vs[kk][d4 * 4] = *(const float4*)((const float*)src + 256);
        }
        __syncthreads();
        for (int kk = 0; kk < kt; kk += 4) {
            float4 b4 = *(const float4*)(brow + k0 + kk);
            float bb[4] = {b4.x, b4.y, b4.z, b4.w};
            #pragma unroll
            for (int u = 0; u < 4; u++) {
                const ulonglong2* kp = (const ulonglong2*)ks[kk + u];
                unsigned long long da = 0ull, db = 0ull;
                #pragma unroll
                for (int d = 0; d < 8; d++) {
                    ulonglong2 kv = kp[d];
                    da = ffma2(q2[2 * d], kv.x, da);
                    db = ffma2(q2[2 * d + 1], kv.y, db);
                }
                float2 dra = unpack2(da), drb = unpack2(db);
                float sc = (dra.x + dra.y + drb.x + drb.y) * ATTN_SCALE + bb[u];
                const ulonglong2* vp = (const ulonglong2*)vs[kk + u];
                if (sc <= m) {
                    float p = __expf(sc - m);
                    den += p;
                    unsigned long long p2 = pack2(p, p);
                    #pragma unroll
                    for (int d = 0; d < 8; d++) {
                        ulonglong2 vv = vp[d];
                        acc[2 * d]     = ffma2(p2, vv.x, acc[2 * d]);
                        acc[2 * d + 1] = ffma2(p2, vv.y, acc[2 * d + 1]);
                    }
                } else {
                    float cc = __expf(m - sc);
                    m = sc;
                    den = den * cc + 1.f;
                    unsigned long long c2 = pack2(cc, cc);
                    #pragma unroll
                    for (int d = 0; d < 8; d++) {
                        ulonglong2 vv = vp[d];
                        acc[2 * d]     = ffma2(acc[2 * d], c2, vv.x);
                        acc[2 * d + 1] = ffma2(acc[2 * d + 1], c2, vv.y);
                    }
                }
            }
        }
    }
    int pidx = ((b * cNH + h) * cTB + q) * SPLITS + s;
    g_buf[O_PM + pidx] = m;
    g_buf[O_PDEN + pidx] = den;
    float* pa = g_buf + O_PACC + (size_t)pidx * cDH;
    #pragma unroll
    for (int d = 0; d < 16; d++) {
        float2 t = unpack2(acc[d]);
        pa[2 * d] = t.x;
        pa[2 * d + 1] = t.y;
    }
}

__global__ void k_attn_merge() {
    int q = blockIdx.x, b = blockIdx.y;
    int t = threadIdx.x;
    int h = t >> 5, d = t & 31;
    int base = ((b * cNH + h) * cTB + q) * SPLITS;
    float M = -INFINITY;
    #pragma unroll
    for (int s = 0; s < SPLITS; s++) M = fmaxf(M, g_buf[O_PM + base + s]);
    float den = 0.f, a = 0.f;
    #pragma unroll
    for (int s = 0; s < SPLITS; s++) {
        float w = __expf(g_buf[O_PM + base + s] - M);
        den += g_buf[O_PDEN + base + s] * w;
        a += g_buf[O_PACC + (size_t)(base + s) * cDH + d] * w;
    }
    int r = row_of(b, q);
    g_buf[O_AO + (size_t)r * cD + t] = a / den;
}

// ---------------- GAT kernels (CSR, no atomics) ----------------
// per-row score precompute: A_s/A_d for nodes, A_e for edges. warp per row.
__global__ void __launch_bounds__(256) k_gat_scores(const float* __restrict__ asrc,
                                                    const float* __restrict__ adst,
                                                    const float* __restrict__ aedge) {
    int warp = threadIdx.x >> 5, lane = threadIdx.x & 31;
    int r = blockIdx.x * 8 + warp;
    int h = lane >> 2, qq = lane & 3;
    int off = h * cDH + qq * 8;
    if (r < cTn) {
        const float4* xp = (const float4*)(g_buf + O_HN + (size_t)r * cD + off);
        float4 x0 = xp[0], x1 = xp[1];
        const float4* sp = (const float4*)(asrc + off);
        const float4* dp = (const float4*)(adst + off);
        float4 s0 = sp[0], s1 = sp[1], d0 = dp[0], d1 = dp[1];
        float ss = x0.x*s0.x + x0.y*s0.y + x0.z*s0.z + x0.w*s0.w
                 + x1.x*s1.x + x1.y*s1.y + x1.z*s1.z + x1.w*s1.w;
        float sd = x0.x*d0.x + x0.y*d0.y + x0.z*d0.z + x0.w*d0.w
                 + x1.x*d1.x + x1.y*d1.y + x1.z*d1.z + x1.w*d1.w;
        ss += __shfl_xor_sync(0xffffffffu, ss, 1);
        ss += __shfl_xor_sync(0xffffffffu, ss, 2);
        sd += __shfl_xor_sync(0xffffffffu, sd, 1);
        sd += __shfl_xor_sync(0xffffffffu, sd, 2);
        if (qq == 0) {
            g_As[r * cNH + h] = ss;
            g_Ad[r * cNH + h] = sd;
        }
    } else {
        int e = r - cTn;
        const float4* xp = (const float4*)(g_buf + O_EE + (size_t)e * cD + off);
        float4 x0 = xp[0], x1 = xp[1];
        const float4* ap = (const float4*)(aedge + off);
        float4 a0 = ap[0], a1 = ap[1];
        float se = x0.x*a0.x + x0.y*a0.y + x0.z*a0.z + x0.w*a0.w
                 + x1.x*a1.x + x1.y*a1.y + x1.z*a1.z + x1.w*a1.w;
        se += __shfl_xor_sync(0xffffffffu, se, 1);
        se += __shfl_xor_sync(0xffffffffu, se, 2);
        if (qq == 0) g_Ae[e * cNH + h] = se;
    }
}

// warp per dst node: softmax over incoming edges + weighted aggregate. 4 warps/block.
__global__ void __launch_bounds__(128) k_gat_node() {
    __shared__ float lg_s[4][64 * 8];
    __shared__ float md_s[4][16];
    int warp = threadIdx.x >> 5, lane = threadIdx.x & 31;
    int i = blockIdx.x * 4 + warp;
    int cnt = g_cnt[i];
    const float* hn = g_buf + O_HN;
    const float* ee = g_buf + O_EE;
    if (lane < 8) {
        float m = -INFINITY;
        for (int j = 0; j < cnt; j++) {
            int e = g_list[i * 64 + j];
            int s = g_src[e];
            float lg = g_As[s * cNH + lane] + g_Ad[i * cNH + lane] + g_Ae[e * cNH + lane];
            lg = (lg > 0.f) ? lg : 0.2f * lg;
            lg_s[warp][j * 8 + lane] = lg;
            m = fmaxf(m, lg);
        }
        float den = 0.f;
        for (int j = 0; j < cnt; j++) den += __expf(lg_s[warp][j * 8 + lane] - m);
        md_s[warp][lane] = m;
        md_s[warp][8 + lane] = den + 1e-9f;
    }
    __syncwarp();
    int hh = lane >> 2;
    float m = md_s[warp][hh];
    float dn = md_s[warp][8 + hh];
    float4 a0 = {0, 0, 0, 0}, a1 = {0, 0, 0, 0};
    for (int j = 0; j < cnt; j++) {
        int e = g_list[i * 64 + j];
        int s = g_src[e];
        float alpha = __expf(lg_s[warp][j * 8 + hh] - m) / dn;
        const float4* hp = (const float4*)(hn + (size_t)s * cD + lane * 8);
        const float4* ep = (const float4*)(ee + (size_t)e * cD + lane * 8);
        float4 h0 = hp[0], h1 = hp[1], e0 = ep[0], e1 = ep[1];
        a0.x += alpha * (h0.x + e0.x); a0.y += alpha * (h0.y + e0.y);
        a0.z += alpha * (h0.z + e0.z); a0.w += alpha * (h0.w + e0.w);
        a1.x += alpha * (h1.x + e1.x); a1.y += alpha * (h1.y + e1.y);
        a1.z += alpha * (h1.z + e1.z); a1.w += alpha * (h1.w + e1.w);
    }
    float4* outp = (float4*)(g_buf + O_NAGG + (size_t)i * cD + lane * 8);
    outp[0] = a0; outp[1] = a1;
}

// ---------------- host orchestration ----------------
extern "C" void kernel_launch(void* const* d_in, const int* in_sizes, int n_in,
                              void* d_out, int out_size) {
    const float* features   = (const float*)d_in[0];
    const float* boxes      = (const float*)d_in[1];
    const int*   edge_local = (const int*)  d_in[2];
    const float* nodes0     = (const float*)d_in[3];
    const float* edges0     = (const float*)d_in[4];
    const float* ln1_g      = (const float*)d_in[5];
    const float* ln1_b      = (const float*)d_in[6];
    const float* attn_in_w  = (const float*)d_in[7];
    const float* attn_in_b  = (const float*)d_in[8];
    const float* attn_out_w = (const float*)d_in[9];
    const float* attn_out_b = (const float*)d_in[10];
    const float* ls1        = (const float*)d_in[11];
    const float* ln2_g      = (const float*)d_in[12];
    const float* ln2_b      = (const float*)d_in[13];
    const float* gat_wn     = (const float*)d_in[14];
    const float* gat_we     = (const float*)d_in[15];
    const float* gat_a_src  = (const float*)d_in[16];
    const float* gat_a_dst  = (const float*)d_in[17];
    const float* gat_a_edge = (const float*)d_in[18];
    const float* gat_wo     = (const float*)d_in[19];
    const float* gat_bo     = (const float*)d_in[20];
    const float* gat_woe    = (const float*)d_in[21];
    const float* gat_boe    = (const float*)d_in[22];
    const float* ls2        = (const float*)d_in[23];
    const float* ln3_g      = (const float*)d_in[24];
    const float* ln3_b      = (const float*)d_in[25];
    const float* ffn_w1     = (const float*)d_in[26];
    const float* ffn_b1     = (const float*)d_in[27];
    const float* ffn_w2     = (const float*)d_in[28];
    const float* ffn_b2     = (const float*)d_in[29];
    const float* ls3        = (const float*)d_in[30];

    float* buf = nullptr;
    cudaGetSymbolAddress((void**)&buf, g_buf);
    float* out = (float*)d_out;

    const int nTD = cT * cD;

    // -------- precompute (KV layer-0 hoisted to index 3 for ncu visibility) -----
    k_edges<<<(cTe + 255) / 256, 256>>>(edge_local);
    k_csr<<<(cTe + 255) / 256, 256>>>();
    k_node_heat<<<cTn, 256>>>(boxes);
    k_mma<true, 1><<<dim3(512 / 128, cFKV / 128), 256>>>(
        features, attn_in_w + cD * cD, attn_in_b + cD, buf + O_KH,
        nullptr, nullptr, nullptr, cFKV, 512, cD);
    k_edge_heat<<<cTe, 256>>>(boxes);
    k_emb<<<nTD / 256, 256>>>(boxes, nodes0, edges0);

    for (int l = 0; l < cL; l++) {
        const float* Wqkv = attn_in_w + (size_t)l * 3 * cD * cD;
        const float* bqkv = attn_in_b + (size_t)l * 3 * cD;

        // ---- cross attention ----
        k_ln<<<cT / 8, 256>>>(buf + O_Q, ln1_g + l * cD, ln1_b + l * cD,
                              buf + O_X, nullptr, nullptr);
        k_mma<true, 1><<<dim3(cD / 128, cT / 128), 256>>>(
            buf + O_X, Wqkv, bqkv, buf + O_QH, nullptr, nullptr, nullptr, cT, cD, cD);
        if (l > 0) {
            // packed K|V projection: N=512 (Wk rows then Wv rows contiguous)
            k_mma<true, 1><<<dim3(512 / 128, cFKV / 128), 256>>>(
                features, Wqkv + cD * cD, bqkv + cD, buf + O_KH,
                nullptr, nullptr, nullptr, cFKV, 512, cD);
        }
        k_attn_partial<<<dim3(cNH, cB, SPLITS), 96>>>();
        k_attn_merge<<<dim3(cTB, cB), 256>>>();
        // attn_out fused residual: Q += ls1 * (AO @ W^T + b)
        k_mma<true, 3><<<dim3(cD / 128, cT / 128), 256>>>(
            buf + O_AO, attn_out_w + (size_t)l * cD * cD, attn_out_b + l * cD,
            buf + O_Q, nullptr, ls1 + l * cD, nullptr, cT, cD, cD);

        // ---- GAT ----
        k_ln<<<cT / 8, 256>>>(buf + O_Q, ln2_g + l * cD, ln2_b + l * cD,
                              buf + O_X, buf + O_XE, buf + O_EMB);
        k_mma<false, 0><<<dim3(cD / 128, cTn / 128), 256>>>(
            buf + O_XE, gat_wn + (size_t)l * cD * cD, nullptr, buf + O_HN,
            nullptr, nullptr, nullptr, cTn, cD, cD);
        k_mma<false, 0><<<dim3(cD / 128, cTe / 128), 256>>>(
            buf + O_XE + (size_t)cTn * cD, gat_we + (size_t)l * cD * cD, nullptr,
            buf + O_EE, nullptr, nullptr, nullptr, cTe, cD, cD);
        k_gat_scores<<<cT / 8, 256>>>(gat_a_src + l * cD, gat_a_dst + l * cD,
                                      gat_a_edge + l * cD);
        k_gat_node<<<cTn / 4, 128>>>();
        // fused: Q = X + ls2 * (NAGG @ Wo + bo)   rows [0, Tn)
        k_mma<false, 4><<<dim3(cD / 128, cTn / 128), 256>>>(
            buf + O_NAGG, gat_wo + (size_t)l * cD * cD, gat_bo + l * cD,
            buf + O_Q, buf + O_X, ls2 + l * cD, nullptr, cTn, cD, cD);
        // fused: Q = X + ls2 * (EE @ Woe + boe)   rows [Tn, T)
        k_mma<false, 4><<<dim3(cD / 128, cTe / 128), 256>>>(
            buf + O_EE, gat_woe + (size_t)l * cD * cD, gat_boe + l * cD,
            buf + O_Q + (size_t)cTn * cD, buf + O_X + (size_t)cTn * cD,
            ls2 + l * cD, nullptr, cTe, cD, cD);

        // ---- FFN ----
        k_ln<<<cT / 8, 256>>>(buf + O_Q, ln3_g + l * cD, ln3_b + l * cD,
                              buf + O_X, nullptr, nullptr);
        k_mma<false, 2><<<dim3(cFF / 128, cT / 128), 256>>>(
            buf + O_X, ffn_w1 + (size_t)l * cD * cFF, ffn_b1 + l * cFF,
            buf + O_Y1, nullptr, nullptr, nullptr, cT, cFF, cD);
        // ffn2 fused residual + dual store (emits layer output)
        k_mma<false, 3><<<dim3(cD / 128, cT / 128), 256>>>(
            buf + O_Y1, ffn_w2 + (size_t)l * cFF * cD, ffn_b2 + l * cD,
            buf + O_Q, nullptr, ls3 + l * cD, out + (size_t)l * nTD, cT, cD, cFF);
    }
    (void)in_sizes; (void)n_in; (void)out_size;
}

// round 13
// speedup vs baseline: 1.0673x; 1.0673x over previous
#include <cuda_runtime.h>
#include <math.h>

// ---------------- constants ----------------
constexpr int cB = 32, cN = 32, cE = 64, cW = 40, cHgrid = 40, cHW = 1600;
constexpr int cD = 256, cNH = 8, cDH = 32, cL = 6;
constexpr int cTn = cB * cN;          // 1024
constexpr int cTe = cB * cE;          // 2048
constexpr int cT  = cTn + cTe;        // 3072
constexpr int cTB = cN + cE;          // 96 tokens per batch
constexpr int cFF = 1024;
constexpr int cFKV = cB * cHW;        // 51200
constexpr int SPLITS = 8;
constexpr int KSPLIT = cHW / SPLITS;  // 200
constexpr int KTILE = 64;
constexpr float ATTN_SCALE = 0.17677669529663689f; // 1/sqrt(32)
constexpr float LOG1E4 = 9.210340371976184f;

// ---------------- scratch arena ----------------
constexpr size_t SZ_TD = (size_t)cT * cD;           // 786432
constexpr size_t O_Q    = 0;
constexpr size_t O_X    = O_Q    + SZ_TD;
constexpr size_t O_XE   = O_X    + SZ_TD;
constexpr size_t O_TMP  = O_XE   + SZ_TD;
constexpr size_t O_QH   = O_TMP  + SZ_TD;
constexpr size_t O_AO   = O_QH   + SZ_TD;
constexpr size_t O_EMB  = O_AO   + SZ_TD;
constexpr size_t O_BIAS = O_EMB  + SZ_TD;                       // cT*cHW
constexpr size_t O_KH   = O_BIAS + (size_t)cT * cHW;            // cFKV*512 (packed K|V)
constexpr size_t O_Y1   = O_KH   + (size_t)cFKV * 512;          // cT*cFF
constexpr size_t O_HN   = O_Y1   + (size_t)cT * cFF;            // cTn*cD
constexpr size_t O_EE   = O_HN   + (size_t)cTn * cD;            // cTe*cD
constexpr size_t O_NAGG = O_EE   + (size_t)cTe * cD;            // cTn*cD
constexpr size_t O_PM   = O_NAGG + (size_t)cTn * cD;            // B*NH*TB*SPLITS
constexpr size_t SZ_P   = (size_t)cB * cNH * cTB * SPLITS;      // 196608
constexpr size_t O_PDEN = O_PM   + SZ_P;
constexpr size_t O_PACC = O_PDEN + SZ_P;                        // SZ_P*cDH
constexpr size_t O_TOTAL = O_PACC + SZ_P * cDH;

__device__ __align__(16) float g_buf[O_TOTAL];
__device__ int   g_src[cTe];
__device__ int   g_dst[cTe];
__device__ int   g_cnt[cTn];
__device__ int   g_list[cTn * 64];
__device__ float g_As[cTn * cNH];
__device__ float g_Ad[cTn * cNH];
__device__ float g_Ae[cTe * cNH];

// ---------------- helpers ----------------
__device__ __forceinline__ int row_of(int b, int t) {
    return (t < cN) ? b * cN + t : cTn + b * cE + (t - cN);
}

__device__ __forceinline__ void mma8(float* c, const unsigned* a, const unsigned* b) {
    asm volatile(
        "mma.sync.aligned.m16n8k8.row.col.f32.tf32.tf32.f32 "
        "{%0,%1,%2,%3}, {%4,%5,%6,%7}, {%8,%9}, {%0,%1,%2,%3};"
        : "+f"(c[0]), "+f"(c[1]), "+f"(c[2]), "+f"(c[3])
        : "r"(a[0]), "r"(a[1]), "r"(a[2]), "r"(a[3]), "r"(b[0]), "r"(b[1]));
}

__device__ __forceinline__ void cpasync16(unsigned sa, const void* g) {
    asm volatile("cp.async.cg.shared.global [%0], [%1], 16;\n" :: "r"(sa), "l"(g));
}
__device__ __forceinline__ void cpcommit() { asm volatile("cp.async.commit_group;\n"); }
template <int W> __device__ __forceinline__ void cpwait() {
    asm volatile("cp.async.wait_group %0;\n" :: "n"(W));
}

__device__ __forceinline__ unsigned long long ffma2(unsigned long long a,
                                                    unsigned long long b,
                                                    unsigned long long c) {
    unsigned long long d;
    asm("fma.rn.f32x2 %0, %1, %2, %3;" : "=l"(d) : "l"(a), "l"(b), "l"(c));
    return d;
}
__device__ __forceinline__ unsigned long long pack2(float lo, float hi) {
    unsigned long long d;
    asm("mov.b64 %0, {%1, %2};" : "=l"(d) : "f"(lo), "f"(hi));
    return d;
}
__device__ __forceinline__ float2 unpack2(unsigned long long v) {
    float lo, hi;
    asm("mov.b64 {%0, %1}, %2;" : "=f"(lo), "=f"(hi) : "l"(v));
    return make_float2(lo, hi);
}

// ---------------- precompute kernels ----------------
__global__ void k_edges(const int* __restrict__ el) {
    int e = blockIdx.x * blockDim.x + threadIdx.x;
    if (e < cTe) {
        int b = e / cE;
        g_src[e] = el[e] + b * cN;
        g_dst[e] = el[cTe + e] + b * cN;
    }
    if (e < cTn) g_cnt[e] = 0;
}

__global__ void k_csr() {
    int e = blockIdx.x * blockDim.x + threadIdx.x;
    if (e < cTe) {
        int d = g_dst[e];
        int slot = atomicAdd(&g_cnt[d], 1);
        g_list[d * 64 + slot] = e;
    }
}

__global__ void k_node_heat(const float* __restrict__ boxes) {
    int nd = blockIdx.x;
    int t = threadIdx.x;
    __shared__ float hx[cW], hy[cHgrid];
    float cx = boxes[nd * 4 + 0], cy = boxes[nd * 4 + 1];
    float w  = boxes[nd * 4 + 2], h  = boxes[nd * 4 + 3];
    if (t < cW) {
        float gx = (t + 0.5f) / cW;
        float dd = gx - cx;
        hx[t] = expf(-dd * dd / (0.5f * w * w + 1e-6f));
    } else if (t < cW + cHgrid) {
        int y = t - cW;
        float gy = (y + 0.5f) / cHgrid;
        float dd = gy - cy;
        hy[y] = expf(-dd * dd / (0.5f * h * h + 1e-6f));
    }
    __syncthreads();
    float* out = g_buf + O_BIAS + (size_t)nd * cHW;
    for (int i = t; i < cHW; i += blockDim.x)
        out[i] = hy[i / cW] * hx[i % cW];
}

__global__ void k_edge_heat(const float* __restrict__ boxes) {
    int e = blockIdx.x;
    int t = threadIdx.x;
    int s = g_src[e], d = g_dst[e];
    float c1x = boxes[s*4+0], c1y = boxes[s*4+1], w1 = boxes[s*4+2], h1 = boxes[s*4+3];
    float c2x = boxes[d*4+0], c2y = boxes[d*4+1], w2 = boxes[d*4+2], h2 = boxes[d*4+3];
    float ux1 = fminf(c1x - w1*0.5f, c2x - w2*0.5f);
    float uy1 = fminf(c1y - h1*0.5f, c2y - h2*0.5f);
    float ux2 = fmaxf(c1x + w1*0.5f, c2x + w2*0.5f);
    float uy2 = fmaxf(c1y + h1*0.5f, c2y + h2*0.5f);
    float ucx = (ux1 + ux2) * 0.5f, ucy = (uy1 + uy2) * 0.5f;
    float uw = ux2 - ux1, uh = uy2 - uy1;
    __shared__ float hx[cW], hy[cHgrid];
    if (t < cW) {
        float gx = (t + 0.5f) / cW;
        float dd = gx - ucx;
        hx[t] = expf(-dd * dd / (0.5f * uw * uw + 1e-6f));
    } else if (t < cW + cHgrid) {
        int y = t - cW;
        float gy = (y + 0.5f) / cHgrid;
        float dd = gy - ucy;
        hy[y] = expf(-dd * dd / (0.5f * uh * uh + 1e-6f));
    }
    __syncthreads();
    const float* hs = g_buf + O_BIAS + (size_t)s * cHW;
    const float* hd = g_buf + O_BIAS + (size_t)d * cHW;
    float* out = g_buf + O_BIAS + (size_t)(cTn + e) * cHW;
    for (int i = t; i < cHW; i += blockDim.x) {
        float u = hy[i / cW] * hx[i % cW];
        out[i] = fmaxf(fmaxf(hs[i], hd[i]), u);
    }
}

// emb + initial Q fill (nodes0|edges0)
__global__ void k_emb(const float* __restrict__ boxes, const float* __restrict__ nodes0,
                      const float* __restrict__ edges0) {
    int i = blockIdx.x * blockDim.x + threadIdx.x;
    if (i >= cT * cD) return;
    int r = i / cD, ch = i % cD;
    int c = ch >> 6;
    int j = ch & 63;
    int fj = j & 31;
    float v;
    if (r < cTn) {
        v = boxes[r * 4 + c];
        g_buf[O_Q + i] = nodes0[i];
    } else {
        int e = r - cTn;
        v = boxes[g_src[e] * 4 + c] - boxes[g_dst[e] * 4 + c];
        g_buf[O_Q + i] = edges0[i - cTn * cD];
    }
    float fr = expf(-LOG1E4 * (float)fj / 32.0f);
    float ang = v * fr;
    g_buf[O_EMB + i] = (j < 32) ? sinf(ang) : cosf(ang);
}

// LayerNorm: warp per row, 8 rows/block; optional xe = out + emb second output.
__global__ void __launch_bounds__(256) k_ln(const float* __restrict__ in,
                                            const float* __restrict__ gg,
                                            const float* __restrict__ bt,
                                            float* __restrict__ out,
                                            float* __restrict__ xe,
                                            const float* __restrict__ emb) {
    int warp = threadIdx.x >> 5, lane = threadIdx.x & 31;
    size_t r = (size_t)blockIdx.x * 8 + warp;
    const float4* row = (const float4*)(in + r * cD);
    float4 v0 = row[lane * 2], v1 = row[lane * 2 + 1];
    float s = v0.x + v0.y + v0.z + v0.w + v1.x + v1.y + v1.z + v1.w;
    #pragma unroll
    for (int o = 16; o; o >>= 1) s += __shfl_xor_sync(0xffffffffu, s, o);
    float mean = s * (1.0f / cD);
    v0.x -= mean; v0.y -= mean; v0.z -= mean; v0.w -= mean;
    v1.x -= mean; v1.y -= mean; v1.z -= mean; v1.w -= mean;
    float s2 = v0.x*v0.x + v0.y*v0.y + v0.z*v0.z + v0.w*v0.w
             + v1.x*v1.x + v1.y*v1.y + v1.z*v1.z + v1.w*v1.w;
    #pragma unroll
    for (int o = 16; o; o >>= 1) s2 += __shfl_xor_sync(0xffffffffu, s2, o);
    float inv = rsqrtf(s2 * (1.0f / cD) + 1e-5f);
    const float4* g4 = (const float4*)gg;
    const float4* b4 = (const float4*)bt;
    float4 ga = g4[lane * 2], gb = g4[lane * 2 + 1];
    float4 ba = b4[lane * 2], bb = b4[lane * 2 + 1];
    float4 o0, o1;
    o0.x = v0.x * inv * ga.x + ba.x; o0.y = v0.y * inv * ga.y + ba.y;
    o0.z = v0.z * inv * ga.z + ba.z; o0.w = v0.w * inv * ga.w + ba.w;
    o1.x = v1.x * inv * gb.x + bb.x; o1.y = v1.y * inv * gb.y + bb.y;
    o1.z = v1.z * inv * gb.z + bb.z; o1.w = v1.w * inv * gb.w + bb.w;
    float4* po = (float4*)(out + r * cD);
    po[lane * 2] = o0; po[lane * 2 + 1] = o1;
    if (xe) {
        const float4* e4 = (const float4*)(emb + r * cD);
        float4 e0 = e4[lane * 2], e1 = e4[lane * 2 + 1];
        float4 x0, x1;
        x0.x = o0.x + e0.x; x0.y = o0.y + e0.y; x0.z = o0.z + e0.z; x0.w = o0.w + e0.w;
        x1.x = o1.x + e1.x; x1.y = o1.y + e1.y; x1.z = o1.z + e1.z; x1.w = o1.w + e1.w;
        float4* px = (float4*)(xe + r * cD);
        px[lane * 2] = x0; px[lane * 2 + 1] = x1;
    }
}

// ---------------- tf32 tensor-core GEMM, 128x64x16, 3-stage cp.async ----------
// C[M,N] = A[M,K] * op(B); TB: B is [N,K] (op=B^T); !TB: B is [K,N].
// EPI: 0=none, 1=+bias, 2=+bias,gelu, 3: C += ls*(v+bias) (opt dual store D2),
//      4: C = X + ls*(v+bias)
// 256 threads = 8 warps (4M x 2N), warp tile 32x32. Requires M%128==0, N%64==0.
template <bool TB, int EPI>
__global__ void __launch_bounds__(256, 3) k_mma(const float* __restrict__ A,
                                                const float* __restrict__ Bw,
                                                const float* __restrict__ bias,
                                                float* __restrict__ C,
                                                const float* __restrict__ X,
                                                const float* __restrict__ ls,
                                                float* __restrict__ D2,
                                                int M, int N, int K) {
    constexpr int BR = TB ? 64 : 16;
    constexpr int BC = TB ? 20 : 68;
    __shared__ float As[3][128][20];
    __shared__ float Bs[3][BR][BC];
    const int tid = threadIdx.x;
    const int m0 = blockIdx.y * 128, n0 = blockIdx.x * 64;
    const int wid = tid >> 5, lane = tid & 31;
    const int wm = (wid & 3) * 32, wn = (wid >> 2) * 32;
    const int g = lane >> 2, tg = lane & 3;
    float c[2][4][4] = {};

    auto loadA = [&](int st, int k0) {
        #pragma unroll
        for (int h = 0; h < 2; h++) {
            int idx = tid + h * 256;
            int row = idx >> 2, c4 = idx & 3;
            unsigned sa = (unsigned)__cvta_generic_to_shared(&As[st][row][c4 * 4]);
            cpasync16(sa, A + (size_t)(m0 + row) * K + k0 + c4 * 4);
        }
    };
    auto loadB = [&](int st, int k0) {
        if constexpr (TB) {
            int row = tid >> 2, c4 = tid & 3;
            unsigned sa = (unsigned)__cvta_generic_to_shared(&Bs[st][row][c4 * 4]);
            cpasync16(sa, Bw + (size_t)(n0 + row) * K + k0 + c4 * 4);
        } else {
            int row = tid >> 4, c4 = tid & 15;
            unsigned sa = (unsigned)__cvta_generic_to_shared(&Bs[st][row][c4 * 4]);
            cpasync16(sa, Bw + (size_t)(k0 + row) * N + n0 + c4 * 4);
        }
    };

    const int T = K >> 4;
    loadA(0, 0); loadB(0, 0); cpcommit();
    if (T > 1) { loadA(1, 16); loadB(1, 16); cpcommit(); }
    for (int it = 0; it < T; it++) {
        int st = it % 3;
        if (it + 2 < T) {
            int nx = (it + 2) % 3;
            loadA(nx, (it + 2) * 16);
            loadB(nx, (it + 2) * 16);
            cpcommit();
            cpwait<2>();
        } else if (it + 1 < T) {
            cpwait<1>();
        } else {
            cpwait<0>();
        }
        __syncthreads();
        #pragma unroll
        for (int kk = 0; kk < 16; kk += 8) {
            unsigned a[2][4], b[4][2];
            #pragma unroll
            for (int i = 0; i < 2; i++) {
                int m = wm + i * 16 + g;
                a[i][0] = __float_as_uint(As[st][m][kk + tg]);
                a[i][1] = __float_as_uint(As[st][m + 8][kk + tg]);
                a[i][2] = __float_as_uint(As[st][m][kk + tg + 4]);
                a[i][3] = __float_as_uint(As[st][m + 8][kk + tg + 4]);
            }
            #pragma unroll
            for (int j = 0; j < 4; j++) {
                int n = wn + j * 8 + g;
                if constexpr (TB) {
                    b[j][0] = __float_as_uint(Bs[st][n][kk + tg]);
                    b[j][1] = __float_as_uint(Bs[st][n][kk + tg + 4]);
                } else {
                    b[j][0] = __float_as_uint(Bs[st][kk + tg][n]);
                    b[j][1] = __float_as_uint(Bs[st][kk + tg + 4][n]);
                }
            }
            #pragma unroll
            for (int i = 0; i < 2; i++)
                #pragma unroll
                for (int j = 0; j < 4; j++)
                    mma8(c[i][j], a[i], b[j]);
        }
        __syncthreads();
    }
    #pragma unroll
    for (int i = 0; i < 2; i++) {
        #pragma unroll
        for (int j = 0; j < 4; j++) {
            int col = n0 + wn + j * 8 + tg * 2;
            #pragma unroll
            for (int p = 0; p < 4; p++) {
                int row = m0 + wm + i * 16 + g + ((p >= 2) ? 8 : 0);
                int cc = col + (p & 1);
                float v = c[i][j][p];
                if (EPI >= 1) v += bias[cc];
                if (EPI == 2) v = 0.5f * v * (1.0f + erff(v * 0.70710678118654752f));
                size_t idx = (size_t)row * N + cc;
                if (EPI == 3) {
                    float nv = C[idx] + ls[cc] * v;
                    C[idx] = nv;
                    if (D2) D2[idx] = nv;
                } else if (EPI == 4) {
                    C[idx] = X[idx] + ls[cc] * v;
                } else {
                    C[idx] = v;
                }
            }
        }
    }
}

// ---------------- attention (flash-style, key-split, f32x2 packed) ----------------
// K/V packed: row stride 512 floats, K at +0, V at +256
__global__ void __launch_bounds__(96) k_attn_partial() {
    int h = blockIdx.x, b = blockIdx.y, s = blockIdx.z;
    int q = threadIdx.x; // 0..95
    __shared__ __align__(16) float ks[KTILE][32];
    __shared__ __align__(16) float vs[KTILE][32];
    const float* khv = g_buf + O_KH;
    int r = row_of(b, q);
    unsigned long long q2[16];
    {
        const float2* qp = (const float2*)(g_buf + O_QH + (size_t)r * cD + h * cDH);
        #pragma unroll
        for (int d = 0; d < 16; d++) { float2 t = qp[d]; q2[d] = pack2(t.x, t.y); }
    }
    const float* brow = g_buf + O_BIAS + (size_t)r * cHW;
    float m = -INFINITY, den = 0.f;
    unsigned long long acc[16];
    #pragma unroll
    for (int d = 0; d < 16; d++) acc[d] = 0ull;
    int kbeg = s * KSPLIT;
    for (int k0 = kbeg; k0 < kbeg + KSPLIT; k0 += KTILE) {
        int kt = min(KTILE, kbeg + KSPLIT - k0);
        __syncthreads();
        for (int idx = q; idx < kt * 8; idx += 96) {
            int kk = idx >> 3, d4 = idx & 7;
            const float4* src = (const float4*)(khv + (size_t)(b * cHW + k0 + kk) * 512
                                                + h * cDH + d4 * 4);
            *(float4*)&ks[kk][d4 * 4] = src[0];
            *(float4*)&vs[kk][d4 * 4] = *(const float4*)((const float*)src + 256);
        }
        __syncthreads();
        for (int kk = 0; kk < kt; kk += 4) {
            float4 b4 = *(const float4*)(brow + k0 + kk);
            float bb[4] = {b4.x, b4.y, b4.z, b4.w};
            #pragma unroll
            for (int u = 0; u < 4; u++) {
                const ulonglong2* kp = (const ulonglong2*)ks[kk + u];
                unsigned long long da = 0ull, db = 0ull;
                #pragma unroll
                for (int d = 0; d < 8; d++) {
                    ulonglong2 kv = kp[d];
                    da = ffma2(q2[2 * d], kv.x, da);
                    db = ffma2(q2[2 * d + 1], kv.y, db);
                }
                float2 dra = unpack2(da), drb = unpack2(db);
                float sc = (dra.x + dra.y + drb.x + drb.y) * ATTN_SCALE + bb[u];
                const ulonglong2* vp = (const ulonglong2*)vs[kk + u];
                if (sc <= m) {
                    float p = __expf(sc - m);
                    den += p;
                    unsigned long long p2 = pack2(p, p);
                    #pragma unroll
                    for (int d = 0; d < 8; d++) {
                        ulonglong2 vv = vp[d];
                        acc[2 * d]     = ffma2(p2, vv.x, acc[2 * d]);
                        acc[2 * d + 1] = ffma2(p2, vv.y, acc[2 * d + 1]);
                    }
                } else {
                    float cc = __expf(m - sc);
                    m = sc;
                    den = den * cc + 1.f;
                    unsigned long long c2 = pack2(cc, cc);
                    #pragma unroll
                    for (int d = 0; d < 8; d++) {
                        ulonglong2 vv = vp[d];
                        acc[2 * d]     = ffma2(acc[2 * d], c2, vv.x);
                        acc[2 * d + 1] = ffma2(acc[2 * d + 1], c2, vv.y);
                    }
                }
            }
        }
    }
    int pidx = ((b * cNH + h) * cTB + q) * SPLITS + s;
    g_buf[O_PM + pidx] = m;
    g_buf[O_PDEN + pidx] = den;
    float* pa = g_buf + O_PACC + (size_t)pidx * cDH;
    #pragma unroll
    for (int d = 0; d < 16; d++) {
        float2 t = unpack2(acc[d]);
        pa[2 * d] = t.x;
        pa[2 * d + 1] = t.y;
    }
}

__global__ void k_attn_merge() {
    int q = blockIdx.x, b = blockIdx.y;
    int t = threadIdx.x;
    int h = t >> 5, d = t & 31;
    int base = ((b * cNH + h) * cTB + q) * SPLITS;
    float M = -INFINITY;
    #pragma unroll
    for (int s = 0; s < SPLITS; s++) M = fmaxf(M, g_buf[O_PM + base + s]);
    float den = 0.f, a = 0.f;
    #pragma unroll
    for (int s = 0; s < SPLITS; s++) {
        float w = __expf(g_buf[O_PM + base + s] - M);
        den += g_buf[O_PDEN + base + s] * w;
        a += g_buf[O_PACC + (size_t)(base + s) * cDH + d] * w;
    }
    int r = row_of(b, q);
    g_buf[O_AO + (size_t)r * cD + t] = a / den;
}

// ---------------- GAT kernels (CSR, no atomics) ----------------
// per-row score precompute: A_s/A_d for nodes, A_e for edges. warp per row.
__global__ void __launch_bounds__(256) k_gat_scores(const float* __restrict__ asrc,
                                                    const float* __restrict__ adst,
                                                    const float* __restrict__ aedge) {
    int warp = threadIdx.x >> 5, lane = threadIdx.x & 31;
    int r = blockIdx.x * 8 + warp;
    int h = lane >> 2, qq = lane & 3;
    int off = h * cDH + qq * 8;
    if (r < cTn) {
        const float4* xp = (const float4*)(g_buf + O_HN + (size_t)r * cD + off);
        float4 x0 = xp[0], x1 = xp[1];
        const float4* sp = (const float4*)(asrc + off);
        const float4* dp = (const float4*)(adst + off);
        float4 s0 = sp[0], s1 = sp[1], d0 = dp[0], d1 = dp[1];
        float ss = x0.x*s0.x + x0.y*s0.y + x0.z*s0.z + x0.w*s0.w
                 + x1.x*s1.x + x1.y*s1.y + x1.z*s1.z + x1.w*s1.w;
        float sd = x0.x*d0.x + x0.y*d0.y + x0.z*d0.z + x0.w*d0.w
                 + x1.x*d1.x + x1.y*d1.y + x1.z*d1.z + x1.w*d1.w;
        ss += __shfl_xor_sync(0xffffffffu, ss, 1);
        ss += __shfl_xor_sync(0xffffffffu, ss, 2);
        sd += __shfl_xor_sync(0xffffffffu, sd, 1);
        sd += __shfl_xor_sync(0xffffffffu, sd, 2);
        if (qq == 0) {
            g_As[r * cNH + h] = ss;
            g_Ad[r * cNH + h] = sd;
        }
    } else {
        int e = r - cTn;
        const float4* xp = (const float4*)(g_buf + O_EE + (size_t)e * cD + off);
        float4 x0 = xp[0], x1 = xp[1];
        const float4* ap = (const float4*)(aedge + off);
        float4 a0 = ap[0], a1 = ap[1];
        float se = x0.x*a0.x + x0.y*a0.y + x0.z*a0.z + x0.w*a0.w
                 + x1.x*a1.x + x1.y*a1.y + x1.z*a1.z + x1.w*a1.w;
        se += __shfl_xor_sync(0xffffffffu, se, 1);
        se += __shfl_xor_sync(0xffffffffu, se, 2);
        if (qq == 0) g_Ae[e * cNH + h] = se;
    }
}

// warp per dst node: softmax over incoming edges + weighted aggregate. 4 warps/block.
__global__ void __launch_bounds__(128) k_gat_node() {
    __shared__ float lg_s[4][64 * 8];
    __shared__ float md_s[4][16];
    int warp = threadIdx.x >> 5, lane = threadIdx.x & 31;
    int i = blockIdx.x * 4 + warp;
    int cnt = g_cnt[i];
    const float* hn = g_buf + O_HN;
    const float* ee = g_buf + O_EE;
    if (lane < 8) {
        float m = -INFINITY;
        for (int j = 0; j < cnt; j++) {
            int e = g_list[i * 64 + j];
            int s = g_src[e];
            float lg = g_As[s * cNH + lane] + g_Ad[i * cNH + lane] + g_Ae[e * cNH + lane];
            lg = (lg > 0.f) ? lg : 0.2f * lg;
            lg_s[warp][j * 8 + lane] = lg;
            m = fmaxf(m, lg);
        }
        float den = 0.f;
        for (int j = 0; j < cnt; j++) den += __expf(lg_s[warp][j * 8 + lane] - m);
        md_s[warp][lane] = m;
        md_s[warp][8 + lane] = den + 1e-9f;
    }
    __syncwarp();
    int hh = lane >> 2;
    float m = md_s[warp][hh];
    float dn = md_s[warp][8 + hh];
    float4 a0 = {0, 0, 0, 0}, a1 = {0, 0, 0, 0};
    for (int j = 0; j < cnt; j++) {
        int e = g_list[i * 64 + j];
        int s = g_src[e];
        float alpha = __expf(lg_s[warp][j * 8 + hh] - m) / dn;
        const float4* hp = (const float4*)(hn + (size_t)s * cD + lane * 8);
        const float4* ep = (const float4*)(ee + (size_t)e * cD + lane * 8);
        float4 h0 = hp[0], h1 = hp[1], e0 = ep[0], e1 = ep[1];
        a0.x += alpha * (h0.x + e0.x); a0.y += alpha * (h0.y + e0.y);
        a0.z += alpha * (h0.z + e0.z); a0.w += alpha * (h0.w + e0.w);
        a1.x += alpha * (h1.x + e1.x); a1.y += alpha * (h1.y + e1.y);
        a1.z += alpha * (h1.z + e1.z); a1.w += alpha * (h1.w + e1.w);
    }
    float4* outp = (float4*)(g_buf + O_NAGG + (size_t)i * cD + lane * 8);
    outp[0] = a0; outp[1] = a1;
}

// ---------------- host orchestration ----------------
extern "C" void kernel_launch(void* const* d_in, const int* in_sizes, int n_in,
                              void* d_out, int out_size) {
    const float* features   = (const float*)d_in[0];
    const float* boxes      = (const float*)d_in[1];
    const int*   edge_local = (const int*)  d_in[2];
    const float* nodes0     = (const float*)d_in[3];
    const float* edges0     = (const float*)d_in[4];
    const float* ln1_g      = (const float*)d_in[5];
    const float* ln1_b      = (const float*)d_in[6];
    const float* attn_in_w  = (const float*)d_in[7];
    const float* attn_in_b  = (const float*)d_in[8];
    const float* attn_out_w = (const float*)d_in[9];
    const float* attn_out_b = (const float*)d_in[10];
    const float* ls1        = (const float*)d_in[11];
    const float* ln2_g      = (const float*)d_in[12];
    const float* ln2_b      = (const float*)d_in[13];
    const float* gat_wn     = (const float*)d_in[14];
    const float* gat_we     = (const float*)d_in[15];
    const float* gat_a_src  = (const float*)d_in[16];
    const float* gat_a_dst  = (const float*)d_in[17];
    const float* gat_a_edge = (const float*)d_in[18];
    const float* gat_wo     = (const float*)d_in[19];
    const float* gat_bo     = (const float*)d_in[20];
    const float* gat_woe    = (const float*)d_in[21];
    const float* gat_boe    = (const float*)d_in[22];
    const float* ls2        = (const float*)d_in[23];
    const float* ln3_g      = (const float*)d_in[24];
    const float* ln3_b      = (const float*)d_in[25];
    const float* ffn_w1     = (const float*)d_in[26];
    const float* ffn_b1     = (const float*)d_in[27];
    const float* ffn_w2     = (const float*)d_in[28];
    const float* ffn_b2     = (const float*)d_in[29];
    const float* ls3        = (const float*)d_in[30];

    float* buf = nullptr;
    cudaGetSymbolAddress((void**)&buf, g_buf);
    float* out = (float*)d_out;

    const int nTD = cT * cD;

    // -------- precompute (KV layer-0 hoisted to index 3 for ncu visibility) -----
    k_edges<<<(cTe + 255) / 256, 256>>>(edge_local);
    k_csr<<<(cTe + 255) / 256, 256>>>();
    k_node_heat<<<cTn, 256>>>(boxes);
    k_mma<true, 1><<<dim3(512 / 64, cFKV / 128), 256>>>(
        features, attn_in_w + cD * cD, attn_in_b + cD, buf + O_KH,
        nullptr, nullptr, nullptr, cFKV, 512, cD);
    k_edge_heat<<<cTe, 256>>>(boxes);
    k_emb<<<nTD / 256, 256>>>(boxes, nodes0, edges0);

    for (int l = 0; l < cL; l++) {
        const float* Wqkv = attn_in_w + (size_t)l * 3 * cD * cD;
        const float* bqkv = attn_in_b + (size_t)l * 3 * cD;

        // ---- cross attention ----
        k_ln<<<cT / 8, 256>>>(buf + O_Q, ln1_g + l * cD, ln1_b + l * cD,
                              buf + O_X, nullptr, nullptr);
        k_mma<true, 1><<<dim3(cD / 64, cT / 128), 256>>>(
            buf + O_X, Wqkv, bqkv, buf + O_QH, nullptr, nullptr, nullptr, cT, cD, cD);
        if (l > 0) {
            // packed K|V projection: N=512 (Wk rows then Wv rows contiguous)
            k_mma<true, 1><<<dim3(512 / 64, cFKV / 128), 256>>>(
                features, Wqkv + cD * cD, bqkv + cD, buf + O_KH,
                nullptr, nullptr, nullptr, cFKV, 512, cD);
        }
        k_attn_partial<<<dim3(cNH, cB, SPLITS), 96>>>();
        k_attn_merge<<<dim3(cTB, cB), 256>>>();
        // attn_out fused residual: Q += ls1 * (AO @ W^T + b)
        k_mma<true, 3><<<dim3(cD / 64, cT / 128), 256>>>(
            buf + O_AO, attn_out_w + (size_t)l * cD * cD, attn_out_b + l * cD,
            buf + O_Q, nullptr, ls1 + l * cD, nullptr, cT, cD, cD);

        // ---- GAT ----
        k_ln<<<cT / 8, 256>>>(buf + O_Q, ln2_g + l * cD, ln2_b + l * cD,
                              buf + O_X, buf + O_XE, buf + O_EMB);
        k_mma<false, 0><<<dim3(cD / 64, cTn / 128), 256>>>(
            buf + O_XE, gat_wn + (size_t)l * cD * cD, nullptr, buf + O_HN,
            nullptr, nullptr, nullptr, cTn, cD, cD);
        k_mma<false, 0><<<dim3(cD / 64, cTe / 128), 256>>>(
            buf + O_XE + (size_t)cTn * cD, gat_we + (size_t)l * cD * cD, nullptr,
            buf + O_EE, nullptr, nullptr, nullptr, cTe, cD, cD);
        k_gat_scores<<<cT / 8, 256>>>(gat_a_src + l * cD, gat_a_dst + l * cD,
                                      gat_a_edge + l * cD);
        k_gat_node<<<cTn / 4, 128>>>();
        // fused: Q = X + ls2 * (NAGG @ Wo + bo)   rows [0, Tn)
        k_mma<false, 4><<<dim3(cD / 64, cTn / 128), 256>>>(
            buf + O_NAGG, gat_wo + (size_t)l * cD * cD, gat_bo + l * cD,
            buf + O_Q, buf + O_X, ls2 + l * cD, nullptr, cTn, cD, cD);
        // fused: Q = X + ls2 * (EE @ Woe + boe)   rows [Tn, T)
        k_mma<false, 4><<<dim3(cD / 64, cTe / 128), 256>>>(
            buf + O_EE, gat_woe + (size_t)l * cD * cD, gat_boe + l * cD,
            buf + O_Q + (size_t)cTn * cD, buf + O_X + (size_t)cTn * cD,
            ls2 + l * cD, nullptr, cTe, cD, cD);

        // ---- FFN ----
        k_ln<<<cT / 8, 256>>>(buf + O_Q, ln3_g + l * cD, ln3_b + l * cD,
                              buf + O_X, nullptr, nullptr);
        k_mma<false, 2><<<dim3(cFF / 64, cT / 128), 256>>>(
            buf + O_X, ffn_w1 + (size_t)l * cD * cFF, ffn_b1 + l * cFF,
            buf + O_Y1, nullptr, nullptr, nullptr, cT, cFF, cD);
        // ffn2 fused residual + dual store (emits layer output)
        k_mma<false, 3><<<dim3(cD / 64, cT / 128), 256>>>(
            buf + O_Y1, ffn_w2 + (size_t)l * cFF * cD, ffn_b2 + l * cD,
            buf + O_Q, nullptr, ls3 + l * cD, out + (size_t)l * nTD, cT, cD, cFF);
    }
    (void)in_sizes; (void)n_in; (void)out_size;
}

// round 15
// speedup vs baseline: 1.2755x; 1.1950x over previous
#include <cuda_runtime.h>
#include <cuda_bf16.h>
#include <math.h>

// ---------------- constants ----------------
constexpr int cB = 32, cN = 32, cE = 64, cW = 40, cHgrid = 40, cHW = 1600;
constexpr int cD = 256, cNH = 8, cDH = 32, cL = 6;
constexpr int cTn = cB * cN;          // 1024
constexpr int cTe = cB * cE;          // 2048
constexpr int cT  = cTn + cTe;        // 3072
constexpr int cTB = cN + cE;          // 96 tokens per batch
constexpr int cFF = 1024;
constexpr int cFKV = cB * cHW;        // 51200
constexpr int SPLITS = 8;
constexpr int KSPLIT = cHW / SPLITS;  // 200
constexpr int KTILE = 64;
constexpr float ATTN_SCALE = 0.17677669529663689f; // 1/sqrt(32)
constexpr float LOG1E4 = 9.210340371976184f;

// ---------------- fp32 scratch arena ----------------
constexpr size_t SZ_TD = (size_t)cT * cD;           // 786432
constexpr size_t O_Q    = 0;
constexpr size_t O_X    = O_Q    + SZ_TD;
constexpr size_t O_QH   = O_X    + SZ_TD;
constexpr size_t O_EMB  = O_QH   + SZ_TD;
constexpr size_t O_BIAS = O_EMB  + SZ_TD;                       // cT*cHW
constexpr size_t O_KH   = O_BIAS + (size_t)cT * cHW;            // cFKV*512 (packed K|V)
constexpr size_t O_HN   = O_KH   + (size_t)cFKV * 512;          // cTn*cD
constexpr size_t O_EE   = O_HN   + (size_t)cTn * cD;            // cTe*cD
constexpr size_t O_PM   = O_EE   + (size_t)cTe * cD;
constexpr size_t SZ_P   = (size_t)cB * cNH * cTB * SPLITS;      // 196608
constexpr size_t O_PDEN = O_PM   + SZ_P;
constexpr size_t O_PACC = O_PDEN + SZ_P;                        // SZ_P*cDH
constexpr size_t O_TOTAL = O_PACC + SZ_P * cDH;

__device__ __align__(16) float g_buf[O_TOTAL];

// ---------------- bf16 arena ----------------
constexpr size_t B_FEAT = 0;                                    // cFKV*cD
constexpr size_t B_WQKV = B_FEAT + (size_t)cFKV * cD;           // 6*768*256
constexpr size_t B_WAO  = B_WQKV + (size_t)cL * 768 * cD;       // 6*256*256
constexpr size_t B_WGN  = B_WAO  + (size_t)cL * cD * cD;
constexpr size_t B_WGE  = B_WGN  + (size_t)cL * cD * cD;
constexpr size_t B_WGO  = B_WGE  + (size_t)cL * cD * cD;
constexpr size_t B_WGOE = B_WGO  + (size_t)cL * cD * cD;
constexpr size_t B_WF1  = B_WGOE + (size_t)cL * cD * cD;        // 6*1024*256 ([N,K])
constexpr size_t B_WF2  = B_WF1  + (size_t)cL * cFF * cD;       // 6*256*1024 ([N,K])
constexpr size_t B_X    = B_WF2  + (size_t)cL * cD * cFF;       // cT*cD
constexpr size_t B_XE   = B_X    + SZ_TD;
constexpr size_t B_AO   = B_XE   + SZ_TD;
constexpr size_t B_Y1   = B_AO   + SZ_TD;                       // cT*cFF
constexpr size_t B_NAGG = B_Y1   + (size_t)cT * cFF;            // cTn*cD
constexpr size_t B_EE   = B_NAGG + (size_t)cTn * cD;            // cTe*cD
constexpr size_t B_TOTAL = B_EE + (size_t)cTe * cD;

__device__ __align__(16) __nv_bfloat16 g_bf[B_TOTAL];

__device__ int   g_src[cTe];
__device__ int   g_dst[cTe];
__device__ int   g_cnt[cTn];
__device__ int   g_list[cTn * 64];
__device__ float g_As[cTn * cNH];
__device__ float g_Ad[cTn * cNH];
__device__ float g_Ae[cTe * cNH];

// ---------------- helpers ----------------
__device__ __forceinline__ int row_of(int b, int t) {
    return (t < cN) ? b * cN + t : cTn + b * cE + (t - cN);
}

__device__ __forceinline__ unsigned bf2u(float lo, float hi) {
    __nv_bfloat162 t = __floats2bfloat162_rn(lo, hi);
    return *reinterpret_cast<unsigned*>(&t);
}

__device__ __forceinline__ void mma16(float* c, const unsigned* a, const unsigned* b) {
    asm volatile(
        "mma.sync.aligned.m16n8k16.row.col.f32.bf16.bf16.f32 "
        "{%0,%1,%2,%3}, {%4,%5,%6,%7}, {%8,%9}, {%0,%1,%2,%3};"
        : "+f"(c[0]), "+f"(c[1]), "+f"(c[2]), "+f"(c[3])
        : "r"(a[0]), "r"(a[1]), "r"(a[2]), "r"(a[3]), "r"(b[0]), "r"(b[1]));
}

__device__ __forceinline__ void cpasync16(unsigned sa, const void* g) {
    asm volatile("cp.async.cg.shared.global [%0], [%1], 16;\n" :: "r"(sa), "l"(g));
}
__device__ __forceinline__ void cpcommit() { asm volatile("cp.async.commit_group;\n"); }
template <int W> __device__ __forceinline__ void cpwait() {
    asm volatile("cp.async.wait_group %0;\n" :: "n"(W));
}

__device__ __forceinline__ unsigned long long ffma2(unsigned long long a,
                                                    unsigned long long b,
                                                    unsigned long long c) {
    unsigned long long d;
    asm("fma.rn.f32x2 %0, %1, %2, %3;" : "=l"(d) : "l"(a), "l"(b), "l"(c));
    return d;
}
__device__ __forceinline__ unsigned long long pack2(float lo, float hi) {
    unsigned long long d;
    asm("mov.b64 %0, {%1, %2};" : "=l"(d) : "f"(lo), "f"(hi));
    return d;
}
__device__ __forceinline__ float2 unpack2(unsigned long long v) {
    float lo, hi;
    asm("mov.b64 {%0, %1}, %2;" : "=f"(lo), "=f"(hi) : "l"(v));
    return make_float2(lo, hi);
}

// ---------------- conversion kernels ----------------
__global__ void k_cvt(const float* __restrict__ in, __nv_bfloat16* __restrict__ o, int n4) {
    int i = blockIdx.x * blockDim.x + threadIdx.x;
    if (i < n4) {
        float4 v = ((const float4*)in)[i];
        __nv_bfloat162 lo = __floats2bfloat162_rn(v.x, v.y);
        __nv_bfloat162 hi = __floats2bfloat162_rn(v.z, v.w);
        ((__nv_bfloat162*)o)[i * 2] = lo;
        ((__nv_bfloat162*)o)[i * 2 + 1] = hi;
    }
}

// batched transpose-convert: in [L][R][C] f32 -> out [L][C][R] bf16. R,C %32==0.
__global__ void k_cvt_t(const float* __restrict__ in, __nv_bfloat16* __restrict__ o,
                        int R, int C) {
    __shared__ float t[32][33];
    int l = blockIdx.z;
    int r0 = blockIdx.y * 32, c0 = blockIdx.x * 32;
    const float* src = in + (size_t)l * R * C;
    __nv_bfloat16* dst = o + (size_t)l * R * C;
    int tx = threadIdx.x, ty = threadIdx.y;
    #pragma unroll
    for (int i = 0; i < 32; i += 8)
        t[ty + i][tx] = src[(size_t)(r0 + ty + i) * C + c0 + tx];
    __syncthreads();
    #pragma unroll
    for (int i = 0; i < 32; i += 8)
        dst[(size_t)(c0 + ty + i) * R + r0 + tx] = __float2bfloat16(t[tx][ty + i]);
}

// ---------------- precompute kernels ----------------
__global__ void k_edges(const int* __restrict__ el) {
    int e = blockIdx.x * blockDim.x + threadIdx.x;
    if (e < cTe) {
        int b = e / cE;
        g_src[e] = el[e] + b * cN;
        g_dst[e] = el[cTe + e] + b * cN;
    }
    if (e < cTn) g_cnt[e] = 0;
}

__global__ void k_csr() {
    int e = blockIdx.x * blockDim.x + threadIdx.x;
    if (e < cTe) {
        int d = g_dst[e];
        int slot = atomicAdd(&g_cnt[d], 1);
        g_list[d * 64 + slot] = e;
    }
}

__global__ void k_node_heat(const float* __restrict__ boxes) {
    int nd = blockIdx.x;
    int t = threadIdx.x;
    __shared__ float hx[cW], hy[cHgrid];
    float cx = boxes[nd * 4 + 0], cy = boxes[nd * 4 + 1];
    float w  = boxes[nd * 4 + 2], h  = boxes[nd * 4 + 3];
    if (t < cW) {
        float gx = (t + 0.5f) / cW;
        float dd = gx - cx;
        hx[t] = expf(-dd * dd / (0.5f * w * w + 1e-6f));
    } else if (t < cW + cHgrid) {
        int y = t - cW;
        float gy = (y + 0.5f) / cHgrid;
        float dd = gy - cy;
        hy[y] = expf(-dd * dd / (0.5f * h * h + 1e-6f));
    }
    __syncthreads();
    float* out = g_buf + O_BIAS + (size_t)nd * cHW;
    for (int i = t; i < cHW; i += blockDim.x)
        out[i] = hy[i / cW] * hx[i % cW];
}

__global__ void k_edge_heat(const float* __restrict__ boxes) {
    int e = blockIdx.x;
    int t = threadIdx.x;
    int s = g_src[e], d = g_dst[e];
    float c1x = boxes[s*4+0], c1y = boxes[s*4+1], w1 = boxes[s*4+2], h1 = boxes[s*4+3];
    float c2x = boxes[d*4+0], c2y = boxes[d*4+1], w2 = boxes[d*4+2], h2 = boxes[d*4+3];
    float ux1 = fminf(c1x - w1*0.5f, c2x - w2*0.5f);
    float uy1 = fminf(c1y - h1*0.5f, c2y - h2*0.5f);
    float ux2 = fmaxf(c1x + w1*0.5f, c2x + w2*0.5f);
    float uy2 = fmaxf(c1y + h1*0.5f, c2y + h2*0.5f);
    float ucx = (ux1 + ux2) * 0.5f, ucy = (uy1 + uy2) * 0.5f;
    float uw = ux2 - ux1, uh = uy2 - uy1;
    __shared__ float hx[cW], hy[cHgrid];
    if (t < cW) {
        float gx = (t + 0.5f) / cW;
        float dd = gx - ucx;
        hx[t] = expf(-dd * dd / (0.5f * uw * uw + 1e-6f));
    } else if (t < cW + cHgrid) {
        int y = t - cW;
        float gy = (y + 0.5f) / cHgrid;
        float dd = gy - ucy;
        hy[y] = expf(-dd * dd / (0.5f * uh * uh + 1e-6f));
    }
    __syncthreads();
    const float* hs = g_buf + O_BIAS + (size_t)s * cHW;
    const float* hd = g_buf + O_BIAS + (size_t)d * cHW;
    float* out = g_buf + O_BIAS + (size_t)(cTn + e) * cHW;
    for (int i = t; i < cHW; i += blockDim.x) {
        float u = hy[i / cW] * hx[i % cW];
        out[i] = fmaxf(fmaxf(hs[i], hd[i]), u);
    }
}

// emb + initial Q fill (nodes0|edges0)
__global__ void k_emb(const float* __restrict__ boxes, const float* __restrict__ nodes0,
                      const float* __restrict__ edges0) {
    int i = blockIdx.x * blockDim.x + threadIdx.x;
    if (i >= cT * cD) return;
    int r = i / cD, ch = i % cD;
    int c = ch >> 6;
    int j = ch & 63;
    int fj = j & 31;
    float v;
    if (r < cTn) {
        v = boxes[r * 4 + c];
        g_buf[O_Q + i] = nodes0[i];
    } else {
        int e = r - cTn;
        v = boxes[g_src[e] * 4 + c] - boxes[g_dst[e] * 4 + c];
        g_buf[O_Q + i] = edges0[i - cTn * cD];
    }
    float fr = expf(-LOG1E4 * (float)fj / 32.0f);
    float ang = v * fr;
    g_buf[O_EMB + i] = (j < 32) ? sinf(ang) : cosf(ang);
}

// LayerNorm: warp per row, 8 rows/block.
// outf: optional f32 out; outb: optional bf16 out; xeb: optional bf16 (out+emb).
__global__ void __launch_bounds__(256) k_ln(const float* __restrict__ in,
                                            const float* __restrict__ gg,
                                            const float* __restrict__ bt,
                                            float* __restrict__ outf,
                                            __nv_bfloat16* __restrict__ outb,
                                            __nv_bfloat16* __restrict__ xeb,
                                            const float* __restrict__ emb) {
    int warp = threadIdx.x >> 5, lane = threadIdx.x & 31;
    size_t r = (size_t)blockIdx.x * 8 + warp;
    const float4* row = (const float4*)(in + r * cD);
    float4 v0 = row[lane * 2], v1 = row[lane * 2 + 1];
    float s = v0.x + v0.y + v0.z + v0.w + v1.x + v1.y + v1.z + v1.w;
    #pragma unroll
    for (int o = 16; o; o >>= 1) s += __shfl_xor_sync(0xffffffffu, s, o);
    float mean = s * (1.0f / cD);
    v0.x -= mean; v0.y -= mean; v0.z -= mean; v0.w -= mean;
    v1.x -= mean; v1.y -= mean; v1.z -= mean; v1.w -= mean;
    float s2 = v0.x*v0.x + v0.y*v0.y + v0.z*v0.z + v0.w*v0.w
             + v1.x*v1.x + v1.y*v1.y + v1.z*v1.z + v1.w*v1.w;
    #pragma unroll
    for (int o = 16; o; o >>= 1) s2 += __shfl_xor_sync(0xffffffffu, s2, o);
    float inv = rsqrtf(s2 * (1.0f / cD) + 1e-5f);
    const float4* g4 = (const float4*)gg;
    const float4* b4 = (const float4*)bt;
    float4 ga = g4[lane * 2], gb = g4[lane * 2 + 1];
    float4 ba = b4[lane * 2], bb = b4[lane * 2 + 1];
    float4 o0, o1;
    o0.x = v0.x * inv * ga.x + ba.x; o0.y = v0.y * inv * ga.y + ba.y;
    o0.z = v0.z * inv * ga.z + ba.z; o0.w = v0.w * inv * ga.w + ba.w;
    o1.x = v1.x * inv * gb.x + bb.x; o1.y = v1.y * inv * gb.y + bb.y;
    o1.z = v1.z * inv * gb.z + bb.z; o1.w = v1.w * inv * gb.w + bb.w;
    if (outf) {
        float4* po = (float4*)(outf + r * cD);
        po[lane * 2] = o0; po[lane * 2 + 1] = o1;
    }
    if (outb) {
        uint4 pk;
        pk.x = bf2u(o0.x, o0.y);
        pk.y = bf2u(o0.z, o0.w);
        pk.z = bf2u(o1.x, o1.y);
        pk.w = bf2u(o1.z, o1.w);
        ((uint4*)(outb + r * cD))[lane] = pk;
    }
    if (xeb) {
        const float4* e4 = (const float4*)(emb + r * cD);
        float4 e0 = e4[lane * 2], e1 = e4[lane * 2 + 1];
        uint4 pk;
        pk.x = bf2u(o0.x + e0.x, o0.y + e0.y);
        pk.y = bf2u(o0.z + e0.z, o0.w + e0.w);
        pk.z = bf2u(o1.x + e1.x, o1.y + e1.y);
        pk.w = bf2u(o1.z + e1.z, o1.w + e1.w);
        ((uint4*)(xeb + r * cD))[lane] = pk;
    }
}

// ---------------- bf16 tensor-core GEMM, 128x64x32, 3-stage cp.async ----------
// C[M,N] = A[M,K] * B^T (+bias). A [M,K] bf16 row-major, B [N,K] bf16 row-major.
// EPI: 0: Cf = v            (HN)
//      1: Cf = v+bias       (QH, KH)
//      2: Cb = gelu(v+bias) (Y1)
//      3: Cf += ls*(v+bias), opt dual store D2 (attn_out, ffn2)
//      4: Cf = X + ls*(v+bias) (gat outs)
//      5: Cf = v; Cb = v    (EE)
// 256 threads, 8 warps (4M x 2N), warp tile 32x32, mma m16n8k16.
template <int EPI>
__global__ void __launch_bounds__(256, 3) k_mma(const __nv_bfloat16* __restrict__ A,
                                                const __nv_bfloat16* __restrict__ Bw,
                                                const float* __restrict__ bias,
                                                float* __restrict__ Cf,
                                                __nv_bfloat16* __restrict__ Cb,
                                                const float* __restrict__ X,
                                                const float* __restrict__ ls,
                                                float* __restrict__ D2,
                                                int M, int N, int K) {
    __shared__ __nv_bfloat16 As[3][128][40];
    __shared__ __nv_bfloat16 Bs[3][64][40];
    const int tid = threadIdx.x;
    const int m0 = blockIdx.y * 128, n0 = blockIdx.x * 64;
    const int wid = tid >> 5, lane = tid & 31;
    const int wm = (wid & 3) * 32, wn = (wid >> 2) * 32;
    const int g = lane >> 2, tg = lane & 3;
    float c[2][4][4] = {};

    auto loadA = [&](int st, int k0) {
        #pragma unroll
        for (int h = 0; h < 2; h++) {
            int idx = tid + h * 256;
            int row = idx >> 2, c4 = idx & 3;
            unsigned sa = (unsigned)__cvta_generic_to_shared(&As[st][row][c4 * 8]);
            cpasync16(sa, A + (size_t)(m0 + row) * K + k0 + c4 * 8);
        }
    };
    auto loadB = [&](int st, int k0) {
        int row = tid >> 2, c4 = tid & 3;
        unsigned sa = (unsigned)__cvta_generic_to_shared(&Bs[st][row][c4 * 8]);
        cpasync16(sa, Bw + (size_t)(n0 + row) * K + k0 + c4 * 8);
    };

    const int T = K >> 5;   // 32 k per iter
    loadA(0, 0); loadB(0, 0); cpcommit();
    if (T > 1) { loadA(1, 32); loadB(1, 32); cpcommit(); }
    for (int it = 0; it < T; it++) {
        int st = it % 3;
        if (it + 2 < T) {
            int nx = (it + 2) % 3;
            loadA(nx, (it + 2) * 32);
            loadB(nx, (it + 2) * 32);
            cpcommit();
            cpwait<2>();
        } else if (it + 1 < T) {
            cpwait<1>();
        } else {
            cpwait<0>();
        }
        __syncthreads();
        #pragma unroll
        for (int ks = 0; ks < 32; ks += 16) {
            unsigned a[2][4], b[4][2];
            #pragma unroll
            for (int i = 0; i < 2; i++) {
                int m = wm + i * 16 + g;
                a[i][0] = *(const unsigned*)&As[st][m][ks + 2 * tg];
                a[i][1] = *(const unsigned*)&As[st][m + 8][ks + 2 * tg];
                a[i][2] = *(const unsigned*)&As[st][m][ks + 2 * tg + 8];
                a[i][3] = *(const unsigned*)&As[st][m + 8][ks + 2 * tg + 8];
            }
            #pragma unroll
            for (int j = 0; j < 4; j++) {
                int n = wn + j * 8 + g;
                b[j][0] = *(const unsigned*)&Bs[st][n][ks + 2 * tg];
                b[j][1] = *(const unsigned*)&Bs[st][n][ks + 2 * tg + 8];
            }
            #pragma unroll
            for (int i = 0; i < 2; i++)
                #pragma unroll
                for (int j = 0; j < 4; j++)
                    mma16(c[i][j], a[i], b[j]);
        }
        __syncthreads();
    }
    #pragma unroll
    for (int i = 0; i < 2; i++) {
        #pragma unroll
        for (int j = 0; j < 4; j++) {
            int col = n0 + wn + j * 8 + tg * 2;
            #pragma unroll
            for (int p = 0; p < 4; p++) {
                int row = m0 + wm + i * 16 + g + ((p >= 2) ? 8 : 0);
                int cc = col + (p & 1);
                float v = c[i][j][p];
                if (EPI == 1 || EPI == 2 || EPI == 3 || EPI == 4) v += bias[cc];
                size_t idx = (size_t)row * N + cc;
                if (EPI == 0) {
                    Cf[idx] = v;
                } else if (EPI == 1) {
                    Cf[idx] = v;
                } else if (EPI == 2) {
                    float gv = 0.5f * v * (1.0f + erff(v * 0.70710678118654752f));
                    Cb[idx] = __float2bfloat16(gv);
                } else if (EPI == 3) {
                    float nv = Cf[idx] + ls[cc] * v;
                    Cf[idx] = nv;
                    if (D2) D2[idx] = nv;
                } else if (EPI == 4) {
                    Cf[idx] = X[idx] + ls[cc] * v;
                } else if (EPI == 5) {
                    Cf[idx] = v;
                    Cb[idx] = __float2bfloat16(v);
                }
            }
        }
    }
}

// ---------------- attention (flash-style, key-split, f32x2 packed) ----------------
// K/V packed: row stride 512 floats, K at +0, V at +256
__global__ void __launch_bounds__(96) k_attn_partial() {
    int h = blockIdx.x, b = blockIdx.y, s = blockIdx.z;
    int q = threadIdx.x; // 0..95
    __shared__ __align__(16) float ks[KTILE][32];
    __shared__ __align__(16) float vs[KTILE][32];
    const float* khv = g_buf + O_KH;
    int r = row_of(b, q);
    unsigned long long q2[16];
    {
        const float2* qp = (const float2*)(g_buf + O_QH + (size_t)r * cD + h * cDH);
        #pragma unroll
        for (int d = 0; d < 16; d++) { float2 t = qp[d]; q2[d] = pack2(t.x, t.y); }
    }
    const float* brow = g_buf + O_BIAS + (size_t)r * cHW;
    float m = -INFINITY, den = 0.f;
    unsigned long long acc[16];
    #pragma unroll
    for (int d = 0; d < 16; d++) acc[d] = 0ull;
    int kbeg = s * KSPLIT;
    for (int k0 = kbeg; k0 < kbeg + KSPLIT; k0 += KTILE) {
        int kt = min(KTILE, kbeg + KSPLIT - k0);
        __syncthreads();
        for (int idx = q; idx < kt * 8; idx += 96) {
            int kk = idx >> 3, d4 = idx & 7;
            const float4* src = (const float4*)(khv + (size_t)(b * cHW + k0 + kk) * 512
                                                + h * cDH + d4 * 4);
            *(float4*)&ks[kk][d4 * 4] = src[0];
            *(float4*)&vs[kk][d4 * 4] = *(const float4*)((const float*)src + 256);
        }
        __syncthreads();
        for (int kk = 0; kk < kt; kk += 4) {
            float4 b4 = *(const float4*)(brow + k0 + kk);
            float bb[4] = {b4.x, b4.y, b4.z, b4.w};
            #pragma unroll
            for (int u = 0; u < 4; u++) {
                const ulonglong2* kp = (const ulonglong2*)ks[kk + u];
                unsigned long long da = 0ull, db = 0ull;
                #pragma unroll
                for (int d = 0; d < 8; d++) {
                    ulonglong2 kv = kp[d];
                    da = ffma2(q2[2 * d], kv.x, da);
                    db = ffma2(q2[2 * d + 1], kv.y, db);
                }
                float2 dra = unpack2(da), drb = unpack2(db);
                float sc = (dra.x + dra.y + drb.x + drb.y) * ATTN_SCALE + bb[u];
                const ulonglong2* vp = (const ulonglong2*)vs[kk + u];
                if (sc <= m) {
                    float p = __expf(sc - m);
                    den += p;
                    unsigned long long p2 = pack2(p, p);
                    #pragma unroll
                    for (int d = 0; d < 8; d++) {
                        ulonglong2 vv = vp[d];
                        acc[2 * d]     = ffma2(p2, vv.x, acc[2 * d]);
                        acc[2 * d + 1] = ffma2(p2, vv.y, acc[2 * d + 1]);
                    }
                } else {
                    float cc = __expf(m - sc);
                    m = sc;
                    den = den * cc + 1.f;
                    unsigned long long c2 = pack2(cc, cc);
                    #pragma unroll
                    for (int d = 0; d < 8; d++) {
                        ulonglong2 vv = vp[d];
                        acc[2 * d]     = ffma2(acc[2 * d], c2, vv.x);
                        acc[2 * d + 1] = ffma2(acc[2 * d + 1], c2, vv.y);
                    }
                }
            }
        }
    }
    int pidx = ((b * cNH + h) * cTB + q) * SPLITS + s;
    g_buf[O_PM + pidx] = m;
    g_buf[O_PDEN + pidx] = den;
    float* pa = g_buf + O_PACC + (size_t)pidx * cDH;
    #pragma unroll
    for (int d = 0; d < 16; d++) {
        float2 t = unpack2(acc[d]);
        pa[2 * d] = t.x;
        pa[2 * d + 1] = t.y;
    }
}

// merge -> AO bf16
__global__ void k_attn_merge() {
    int q = blockIdx.x, b = blockIdx.y;
    int t = threadIdx.x;
    int h = t >> 5, d = t & 31;
    int base = ((b * cNH + h) * cTB + q) * SPLITS;
    float M = -INFINITY;
    #pragma unroll
    for (int s = 0; s < SPLITS; s++) M = fmaxf(M, g_buf[O_PM + base + s]);
    float den = 0.f, a = 0.f;
    #pragma unroll
    for (int s = 0; s < SPLITS; s++) {
        float w = __expf(g_buf[O_PM + base + s] - M);
        den += g_buf[O_PDEN + base + s] * w;
        a += g_buf[O_PACC + (size_t)(base + s) * cDH + d] * w;
    }
    int r = row_of(b, q);
    g_bf[B_AO + (size_t)r * cD + t] = __float2bfloat16(a / den);
}

// ---------------- GAT kernels (CSR, no atomics) ----------------
__global__ void __launch_bounds__(256) k_gat_scores(const float* __restrict__ asrc,
                                                    const float* __restrict__ adst,
                                                    const float* __restrict__ aedge) {
    int warp = threadIdx.x >> 5, lane = threadIdx.x & 31;
    int r = blockIdx.x * 8 + warp;
    int h = lane >> 2, qq = lane & 3;
    int off = h * cDH + qq * 8;
    if (r < cTn) {
        const float4* xp = (const float4*)(g_buf + O_HN + (size_t)r * cD + off);
        float4 x0 = xp[0], x1 = xp[1];
        const float4* sp = (const float4*)(asrc + off);
        const float4* dp = (const float4*)(adst + off);
        float4 s0 = sp[0], s1 = sp[1], d0 = dp[0], d1 = dp[1];
        float ss = x0.x*s0.x + x0.y*s0.y + x0.z*s0.z + x0.w*s0.w
                 + x1.x*s1.x + x1.y*s1.y + x1.z*s1.z + x1.w*s1.w;
        float sd = x0.x*d0.x + x0.y*d0.y + x0.z*d0.z + x0.w*d0.w
                 + x1.x*d1.x + x1.y*d1.y + x1.z*d1.z + x1.w*d1.w;
        ss += __shfl_xor_sync(0xffffffffu, ss, 1);
        ss += __shfl_xor_sync(0xffffffffu, ss, 2);
        sd += __shfl_xor_sync(0xffffffffu, sd, 1);
        sd += __shfl_xor_sync(0xffffffffu, sd, 2);
        if (qq == 0) {
            g_As[r * cNH + h] = ss;
            g_Ad[r * cNH + h] = sd;
        }
    } else {
        int e = r - cTn;
        const float4* xp = (const float4*)(g_buf + O_EE + (size_t)e * cD + off);
        float4 x0 = xp[0], x1 = xp[1];
        const float4* ap = (const float4*)(aedge + off);
        float4 a0 = ap[0], a1 = ap[1];
        float se = x0.x*a0.x + x0.y*a0.y + x0.z*a0.z + x0.w*a0.w
                 + x1.x*a1.x + x1.y*a1.y + x1.z*a1.z + x1.w*a1.w;
        se += __shfl_xor_sync(0xffffffffu, se, 1);
        se += __shfl_xor_sync(0xffffffffu, se, 2);
        if (qq == 0) g_Ae[e * cNH + h] = se;
    }
}

// warp per dst node -> NAGG bf16
__global__ void __launch_bounds__(128) k_gat_node() {
    __shared__ float lg_s[4][64 * 8];
    __shared__ float md_s[4][16];
    int warp = threadIdx.x >> 5, lane = threadIdx.x & 31;
    int i = blockIdx.x * 4 + warp;
    int cnt = g_cnt[i];
    const float* hn = g_buf + O_HN;
    const float* ee = g_buf + O_EE;
    if (lane < 8) {
        float m = -INFINITY;
        for (int j = 0; j < cnt; j++) {
            int e = g_list[i * 64 + j];
            int s = g_src[e];
            float lg = g_As[s * cNH + lane] + g_Ad[i * cNH + lane] + g_Ae[e * cNH + lane];
            lg = (lg > 0.f) ? lg : 0.2f * lg;
            lg_s[warp][j * 8 + lane] = lg;
            m = fmaxf(m, lg);
        }
        float den = 0.f;
        for (int j = 0; j < cnt; j++) den += __expf(lg_s[warp][j * 8 + lane] - m);
        md_s[warp][lane] = m;
        md_s[warp][8 + lane] = den + 1e-9f;
    }
    __syncwarp();
    int hh = lane >> 2;
    float m = md_s[warp][hh];
    float dn = md_s[warp][8 + hh];
    float4 a0 = {0, 0, 0, 0}, a1 = {0, 0, 0, 0};
    for (int j = 0; j < cnt; j++) {
        int e = g_list[i * 64 + j];
        int s = g_src[e];
        float alpha = __expf(lg_s[warp][j * 8 + hh] - m) / dn;
        const float4* hp = (const float4*)(hn + (size_t)s * cD + lane * 8);
        const float4* ep = (const float4*)(ee + (size_t)e * cD + lane * 8);
        float4 h0 = hp[0], h1 = hp[1], e0 = ep[0], e1 = ep[1];
        a0.x += alpha * (h0.x + e0.x); a0.y += alpha * (h0.y + e0.y);
        a0.z += alpha * (h0.z + e0.z); a0.w += alpha * (h0.w + e0.w);
        a1.x += alpha * (h1.x + e1.x); a1.y += alpha * (h1.y + e1.y);
        a1.z += alpha * (h1.z + e1.z); a1.w += alpha * (h1.w + e1.w);
    }
    uint4 pk;
    pk.x = bf2u(a0.x, a0.y);
    pk.y = bf2u(a0.z, a0.w);
    pk.z = bf2u(a1.x, a1.y);
    pk.w = bf2u(a1.z, a1.w);
    ((uint4*)(g_bf + B_NAGG + (size_t)i * cD + lane * 8))[0] = pk;
}

// ---------------- host orchestration ----------------
extern "C" void kernel_launch(void* const* d_in, const int* in_sizes, int n_in,
                              void* d_out, int out_size) {
    const float* features   = (const float*)d_in[0];
    const float* boxes      = (const float*)d_in[1];
    const int*   edge_local = (const int*)  d_in[2];
    const float* nodes0     = (const float*)d_in[3];
    const float* edges0     = (const float*)d_in[4];
    const float* ln1_g      = (const float*)d_in[5];
    const float* ln1_b      = (const float*)d_in[6];
    const float* attn_in_w  = (const float*)d_in[7];
    const float* attn_in_b  = (const float*)d_in[8];
    const float* attn_out_w = (const float*)d_in[9];
    const float* attn_out_b = (const float*)d_in[10];
    const float* ls1        = (const float*)d_in[11];
    const float* ln2_g      = (const float*)d_in[12];
    const float* ln2_b      = (const float*)d_in[13];
    const float* gat_wn     = (const float*)d_in[14];
    const float* gat_we     = (const float*)d_in[15];
    const float* gat_a_src  = (const float*)d_in[16];
    const float* gat_a_dst  = (const float*)d_in[17];
    const float* gat_a_edge = (const float*)d_in[18];
    const float* gat_wo     = (const float*)d_in[19];
    const float* gat_bo     = (const float*)d_in[20];
    const float* gat_woe    = (const float*)d_in[21];
    const float* gat_boe    = (const float*)d_in[22];
    const float* ls2        = (const float*)d_in[23];
    const float* ln3_g      = (const float*)d_in[24];
    const float* ln3_b      = (const float*)d_in[25];
    const float* ffn_w1     = (const float*)d_in[26];
    const float* ffn_b1     = (const float*)d_in[27];
    const float* ffn_w2     = (const float*)d_in[28];
    const float* ffn_b2     = (const float*)d_in[29];
    const float* ls3        = (const float*)d_in[30];

    float* buf = nullptr;
    cudaGetSymbolAddress((void**)&buf, g_buf);
    __nv_bfloat16* bf = nullptr;
    cudaGetSymbolAddress((void**)&bf, g_bf);
    float* out = (float*)d_out;

    const int nTD = cT * cD;

    // -------- precompute (KV layer-0 at launch idx 5 for ncu visibility) -----
    k_edges<<<(cTe + 255) / 256, 256>>>(edge_local);                              // 0
    k_csr<<<(cTe + 255) / 256, 256>>>();                                          // 1
    k_cvt<<<(cFKV * cD / 4 + 255) / 256, 256>>>(features, bf + B_FEAT,            // 2
                                                cFKV * cD / 4);
    k_cvt<<<(cL * 768 * cD / 4 + 255) / 256, 256>>>(attn_in_w, bf + B_WQKV,       // 3
                                                    cL * 768 * cD / 4);
    k_cvt<<<(cL * cD * cD / 4 + 255) / 256, 256>>>(attn_out_w, bf + B_WAO,        // 4
                                                   cL * cD * cD / 4);
    k_mma<1><<<dim3(512 / 64, cFKV / 128), 256>>>(                                // 5 (KV l=0)
        bf + B_FEAT, bf + B_WQKV + cD * cD, attn_in_b + cD,
        buf + O_KH, nullptr, nullptr, nullptr, nullptr, cFKV, 512, cD);
    dim3 tb(32, 8);
    k_cvt_t<<<dim3(8, 8, cL), tb>>>(gat_wn, bf + B_WGN, cD, cD);
    k_cvt_t<<<dim3(8, 8, cL), tb>>>(gat_we, bf + B_WGE, cD, cD);
    k_cvt_t<<<dim3(8, 8, cL), tb>>>(gat_wo, bf + B_WGO, cD, cD);
    k_cvt_t<<<dim3(8, 8, cL), tb>>>(gat_woe, bf + B_WGOE, cD, cD);
    k_cvt_t<<<dim3(32, 8, cL), tb>>>(ffn_w1, bf + B_WF1, cD, cFF);
    k_cvt_t<<<dim3(8, 32, cL), tb>>>(ffn_w2, bf + B_WF2, cFF, cD);
    k_node_heat<<<cTn, 256>>>(boxes);
    k_edge_heat<<<cTe, 256>>>(boxes);
    k_emb<<<nTD / 256, 256>>>(boxes, nodes0, edges0);

    for (int l = 0; l < cL; l++) {
        const __nv_bfloat16* WQ = bf + B_WQKV + (size_t)l * 768 * cD;
        const float* bqkv = attn_in_b + (size_t)l * 3 * cD;

        // ---- cross attention ----
        k_ln<<<cT / 8, 256>>>(buf + O_Q, ln1_g + l * cD, ln1_b + l * cD,
                              nullptr, bf + B_X, nullptr, nullptr);
        k_mma<1><<<dim3(cD / 64, cT / 128), 256>>>(
            bf + B_X, WQ, bqkv, buf + O_QH, nullptr, nullptr, nullptr, nullptr,
            cT, cD, cD);
        if (l > 0) {
            k_mma<1><<<dim3(512 / 64, cFKV / 128), 256>>>(
                bf + B_FEAT, WQ + cD * cD, bqkv + cD, buf + O_KH,
                nullptr, nullptr, nullptr, nullptr, cFKV, 512, cD);
        }
        k_attn_partial<<<dim3(cNH, cB, SPLITS), 96>>>();
        k_attn_merge<<<dim3(cTB, cB), 256>>>();
        // attn_out fused residual: Q += ls1 * (AO @ W^T + b)
        k_mma<3><<<dim3(cD / 64, cT / 128), 256>>>(
            bf + B_AO, bf + B_WAO + (size_t)l * cD * cD, attn_out_b + l * cD,
            buf + O_Q, nullptr, nullptr, ls1 + l * cD, nullptr, cT, cD, cD);

        // ---- GAT ----
        k_ln<<<cT / 8, 256>>>(buf + O_Q, ln2_g + l * cD, ln2_b + l * cD,
                              buf + O_X, nullptr, bf + B_XE, buf + O_EMB);
        k_mma<0><<<dim3(cD / 64, cTn / 128), 256>>>(
            bf + B_XE, bf + B_WGN + (size_t)l * cD * cD, nullptr, buf + O_HN,
            nullptr, nullptr, nullptr, nullptr, cTn, cD, cD);
        k_mma<5><<<dim3(cD / 64, cTe / 128), 256>>>(
            bf + B_XE + (size_t)cTn * cD, bf + B_WGE + (size_t)l * cD * cD, nullptr,
            buf + O_EE, bf + B_EE, nullptr, nullptr, nullptr, cTe, cD, cD);
        k_gat_scores<<<cT / 8, 256>>>(gat_a_src + l * cD, gat_a_dst + l * cD,
                                      gat_a_edge + l * cD);
        k_gat_node<<<cTn / 4, 128>>>();
        // fused: Q = X + ls2 * (NAGG @ Wo + bo)   rows [0, Tn)
        k_mma<4><<<dim3(cD / 64, cTn / 128), 256>>>(
            bf + B_NAGG, bf + B_WGO + (size_t)l * cD * cD, gat_bo + l * cD,
            buf + O_Q, nullptr, buf + O_X, ls2 + l * cD, nullptr, cTn, cD, cD);
        // fused: Q = X + ls2 * (EE @ Woe + boe)   rows [Tn, T)
        k_mma<4><<<dim3(cD / 64, cTe / 128), 256>>>(
            bf + B_EE, bf + B_WGOE + (size_t)l * cD * cD, gat_boe + l * cD,
            buf + O_Q + (size_t)cTn * cD, nullptr, buf + O_X + (size_t)cTn * cD,
            ls2 + l * cD, nullptr, cTe, cD, cD);

        // ---- FFN ----
        k_ln<<<cT / 8, 256>>>(buf + O_Q, ln3_g + l * cD, ln3_b + l * cD,
                              nullptr, bf + B_X, nullptr, nullptr);
        k_mma<2><<<dim3(cFF / 64, cT / 128), 256>>>(
            bf + B_X, bf + B_WF1 + (size_t)l * cFF * cD, ffn_b1 + l * cFF,
            nullptr, bf + B_Y1, nullptr, nullptr, nullptr, cT, cFF, cD);
        // ffn2 fused residual + dual store (emits layer output)
        k_mma<3><<<dim3(cD / 64, cT / 128), 256>>>(
            bf + B_Y1, bf + B_WF2 + (size_t)l * cD * cFF, ffn_b2 + l * cD,
            buf + O_Q, nullptr, nullptr, ls3 + l * cD, out + (size_t)l * nTD,
            cT, cD, cFF);
    }
    (void)in_sizes; (void)n_in; (void)out_size;
}

// round 17
// speedup vs baseline: 1.8579x; 1.4566x over previous
#include <cuda_runtime.h>
#include <cuda_bf16.h>
#include <math.h>

// ---------------- constants ----------------
constexpr int cB = 32, cN = 32, cE = 64, cW = 40, cHgrid = 40, cHW = 1600;
constexpr int cD = 256, cNH = 8, cDH = 32, cL = 6;
constexpr int cTn = cB * cN;          // 1024
constexpr int cTe = cB * cE;          // 2048
constexpr int cT  = cTn + cTe;        // 3072
constexpr int cTB = cN + cE;          // 96 tokens per batch
constexpr int cFF = 1024;
constexpr int cFKV = cB * cHW;        // 51200
constexpr int SPLITS = 5;
constexpr int AKSPLIT = cHW / SPLITS; // 320 keys per split (5 tiles of 64)
constexpr float ATTN_SCALE = 0.17677669529663689f; // 1/sqrt(32)
constexpr float LOG1E4 = 9.210340371976184f;

// ---------------- fp32 scratch arena ----------------
constexpr size_t SZ_TD = (size_t)cT * cD;           // 786432
constexpr size_t O_Q    = 0;
constexpr size_t O_X    = O_Q    + SZ_TD;
constexpr size_t O_EMB  = O_X    + SZ_TD;
constexpr size_t O_BIAS = O_EMB  + SZ_TD;                       // cT*cHW
constexpr size_t O_HN   = O_BIAS + (size_t)cT * cHW;            // cTn*cD
constexpr size_t O_EE   = O_HN   + (size_t)cTn * cD;            // cTe*cD
constexpr size_t O_PM   = O_EE   + (size_t)cTe * cD;
constexpr size_t SZ_P   = (size_t)cB * cNH * cTB * SPLITS;      // 122880
constexpr size_t O_PDEN = O_PM   + SZ_P;
constexpr size_t O_PACC = O_PDEN + SZ_P;                        // SZ_P*cDH
constexpr size_t O_TOTAL = O_PACC + SZ_P * cDH;

__device__ __align__(16) float g_buf[O_TOTAL];

// ---------------- bf16 arena ----------------
constexpr size_t B_FEAT = 0;                                    // cFKV*cD
constexpr size_t B_WQKV = B_FEAT + (size_t)cFKV * cD;           // 6*768*256
constexpr size_t B_WAO  = B_WQKV + (size_t)cL * 768 * cD;       // 6*256*256
constexpr size_t B_WGN  = B_WAO  + (size_t)cL * cD * cD;
constexpr size_t B_WGE  = B_WGN  + (size_t)cL * cD * cD;
constexpr size_t B_WGO  = B_WGE  + (size_t)cL * cD * cD;
constexpr size_t B_WGOE = B_WGO  + (size_t)cL * cD * cD;
constexpr size_t B_WF1  = B_WGOE + (size_t)cL * cD * cD;        // 6*1024*256 ([N,K])
constexpr size_t B_WF2  = B_WF1  + (size_t)cL * cFF * cD;       // 6*256*1024 ([N,K])
constexpr size_t B_X    = B_WF2  + (size_t)cL * cD * cFF;       // cT*cD
constexpr size_t B_XE   = B_X    + SZ_TD;
constexpr size_t B_AO   = B_XE   + SZ_TD;
constexpr size_t B_Y1   = B_AO   + SZ_TD;                       // cT*cFF
constexpr size_t B_NAGG = B_Y1   + (size_t)cT * cFF;            // cTn*cD
constexpr size_t B_EE   = B_NAGG + (size_t)cTn * cD;            // cTe*cD
constexpr size_t B_QH   = B_EE   + (size_t)cTe * cD;            // cT*cD
constexpr size_t B_KH   = B_QH   + SZ_TD;                       // cFKV*512 packed K|V
constexpr size_t B_TOTAL = B_KH + (size_t)cFKV * 512;

__device__ __align__(16) __nv_bfloat16 g_bf[B_TOTAL];

__device__ int   g_src[cTe];
__device__ int   g_dst[cTe];
__device__ int   g_cnt[cTn];
__device__ int   g_list[cTn * 64];
__device__ float g_As[cTn * cNH];
__device__ float g_Ad[cTn * cNH];
__device__ float g_Ae[cTe * cNH];

// ---------------- helpers ----------------
__device__ __forceinline__ int row_of(int b, int t) {
    return (t < cN) ? b * cN + t : cTn + b * cE + (t - cN);
}

__device__ __forceinline__ unsigned bf2u(float lo, float hi) {
    __nv_bfloat162 t = __floats2bfloat162_rn(lo, hi);
    return *reinterpret_cast<unsigned*>(&t);
}

__device__ __forceinline__ void mma16(float* c, const unsigned* a, const unsigned* b) {
    asm volatile(
        "mma.sync.aligned.m16n8k16.row.col.f32.bf16.bf16.f32 "
        "{%0,%1,%2,%3}, {%4,%5,%6,%7}, {%8,%9}, {%0,%1,%2,%3};"
        : "+f"(c[0]), "+f"(c[1]), "+f"(c[2]), "+f"(c[3])
        : "r"(a[0]), "r"(a[1]), "r"(a[2]), "r"(a[3]), "r"(b[0]), "r"(b[1]));
}

__device__ __forceinline__ void cpasync16(unsigned sa, const void* g) {
    asm volatile("cp.async.cg.shared.global [%0], [%1], 16;\n" :: "r"(sa), "l"(g));
}
__device__ __forceinline__ void cpcommit() { asm volatile("cp.async.commit_group;\n"); }
template <int W> __device__ __forceinline__ void cpwait() {
    asm volatile("cp.async.wait_group %0;\n" :: "n"(W));
}

// ---------------- conversion kernels ----------------
__global__ void k_cvt(const float* __restrict__ in, __nv_bfloat16* __restrict__ o, int n4) {
    int i = blockIdx.x * blockDim.x + threadIdx.x;
    if (i < n4) {
        float4 v = ((const float4*)in)[i];
        __nv_bfloat162 lo = __floats2bfloat162_rn(v.x, v.y);
        __nv_bfloat162 hi = __floats2bfloat162_rn(v.z, v.w);
        ((__nv_bfloat162*)o)[i * 2] = lo;
        ((__nv_bfloat162*)o)[i * 2 + 1] = hi;
    }
}

// batched transpose-convert: in [L][R][C] f32 -> out [L][C][R] bf16. R,C %32==0.
__global__ void k_cvt_t(const float* __restrict__ in, __nv_bfloat16* __restrict__ o,
                        int R, int C) {
    __shared__ float t[32][33];
    int l = blockIdx.z;
    int r0 = blockIdx.y * 32, c0 = blockIdx.x * 32;
    const float* src = in + (size_t)l * R * C;
    __nv_bfloat16* dst = o + (size_t)l * R * C;
    int tx = threadIdx.x, ty = threadIdx.y;
    #pragma unroll
    for (int i = 0; i < 32; i += 8)
        t[ty + i][tx] = src[(size_t)(r0 + ty + i) * C + c0 + tx];
    __syncthreads();
    #pragma unroll
    for (int i = 0; i < 32; i += 8)
        dst[(size_t)(c0 + ty + i) * R + r0 + tx] = __float2bfloat16(t[tx][ty + i]);
}

// ---------------- precompute kernels ----------------
__global__ void k_edges(const int* __restrict__ el) {
    int e = blockIdx.x * blockDim.x + threadIdx.x;
    if (e < cTe) {
        int b = e / cE;
        g_src[e] = el[e] + b * cN;
        g_dst[e] = el[cTe + e] + b * cN;
    }
    if (e < cTn) g_cnt[e] = 0;
}

__global__ void k_csr() {
    int e = blockIdx.x * blockDim.x + threadIdx.x;
    if (e < cTe) {
        int d = g_dst[e];
        int slot = atomicAdd(&g_cnt[d], 1);
        g_list[d * 64 + slot] = e;
    }
}

__global__ void k_node_heat(const float* __restrict__ boxes) {
    int nd = blockIdx.x;
    int t = threadIdx.x;
    __shared__ float hx[cW], hy[cHgrid];
    float cx = boxes[nd * 4 + 0], cy = boxes[nd * 4 + 1];
    float w  = boxes[nd * 4 + 2], h  = boxes[nd * 4 + 3];
    if (t < cW) {
        float gx = (t + 0.5f) / cW;
        float dd = gx - cx;
        hx[t] = expf(-dd * dd / (0.5f * w * w + 1e-6f));
    } else if (t < cW + cHgrid) {
        int y = t - cW;
        float gy = (y + 0.5f) / cHgrid;
        float dd = gy - cy;
        hy[y] = expf(-dd * dd / (0.5f * h * h + 1e-6f));
    }
    __syncthreads();
    float* out = g_buf + O_BIAS + (size_t)nd * cHW;
    for (int i = t; i < cHW; i += blockDim.x)
        out[i] = hy[i / cW] * hx[i % cW];
}

__global__ void k_edge_heat(const float* __restrict__ boxes) {
    int e = blockIdx.x;
    int t = threadIdx.x;
    int s = g_src[e], d = g_dst[e];
    float c1x = boxes[s*4+0], c1y = boxes[s*4+1], w1 = boxes[s*4+2], h1 = boxes[s*4+3];
    float c2x = boxes[d*4+0], c2y = boxes[d*4+1], w2 = boxes[d*4+2], h2 = boxes[d*4+3];
    float ux1 = fminf(c1x - w1*0.5f, c2x - w2*0.5f);
    float uy1 = fminf(c1y - h1*0.5f, c2y - h2*0.5f);
    float ux2 = fmaxf(c1x + w1*0.5f, c2x + w2*0.5f);
    float uy2 = fmaxf(c1y + h1*0.5f, c2y + h2*0.5f);
    float ucx = (ux1 + ux2) * 0.5f, ucy = (uy1 + uy2) * 0.5f;
    float uw = ux2 - ux1, uh = uy2 - uy1;
    __shared__ float hx[cW], hy[cHgrid];
    if (t < cW) {
        float gx = (t + 0.5f) / cW;
        float dd = gx - ucx;
        hx[t] = expf(-dd * dd / (0.5f * uw * uw + 1e-6f));
    } else if (t < cW + cHgrid) {
        int y = t - cW;
        float gy = (y + 0.5f) / cHgrid;
        float dd = gy - ucy;
        hy[y] = expf(-dd * dd / (0.5f * uh * uh + 1e-6f));
    }
    __syncthreads();
    const float* hs = g_buf + O_BIAS + (size_t)s * cHW;
    const float* hd = g_buf + O_BIAS + (size_t)d * cHW;
    float* out = g_buf + O_BIAS + (size_t)(cTn + e) * cHW;
    for (int i = t; i < cHW; i += blockDim.x) {
        float u = hy[i / cW] * hx[i % cW];
        out[i] = fmaxf(fmaxf(hs[i], hd[i]), u);
    }
}

// emb + initial Q fill (nodes0|edges0)
__global__ void k_emb(const float* __restrict__ boxes, const float* __restrict__ nodes0,
                      const float* __restrict__ edges0) {
    int i = blockIdx.x * blockDim.x + threadIdx.x;
    if (i >= cT * cD) return;
    int r = i / cD, ch = i % cD;
    int c = ch >> 6;
    int j = ch & 63;
    int fj = j & 31;
    float v;
    if (r < cTn) {
        v = boxes[r * 4 + c];
        g_buf[O_Q + i] = nodes0[i];
    } else {
        int e = r - cTn;
        v = boxes[g_src[e] * 4 + c] - boxes[g_dst[e] * 4 + c];
        g_buf[O_Q + i] = edges0[i - cTn * cD];
    }
    float fr = expf(-LOG1E4 * (float)fj / 32.0f);
    float ang = v * fr;
    g_buf[O_EMB + i] = (j < 32) ? sinf(ang) : cosf(ang);
}

// LayerNorm: warp per row, 8 rows/block.
// outf: optional f32 out; outb: optional bf16 out; xeb: optional bf16 (out+emb).
__global__ void __launch_bounds__(256) k_ln(const float* __restrict__ in,
                                            const float* __restrict__ gg,
                                            const float* __restrict__ bt,
                                            float* __restrict__ outf,
                                            __nv_bfloat16* __restrict__ outb,
                                            __nv_bfloat16* __restrict__ xeb,
                                            const float* __restrict__ emb) {
    int warp = threadIdx.x >> 5, lane = threadIdx.x & 31;
    size_t r = (size_t)blockIdx.x * 8 + warp;
    const float4* row = (const float4*)(in + r * cD);
    float4 v0 = row[lane * 2], v1 = row[lane * 2 + 1];
    float s = v0.x + v0.y + v0.z + v0.w + v1.x + v1.y + v1.z + v1.w;
    #pragma unroll
    for (int o = 16; o; o >>= 1) s += __shfl_xor_sync(0xffffffffu, s, o);
    float mean = s * (1.0f / cD);
    v0.x -= mean; v0.y -= mean; v0.z -= mean; v0.w -= mean;
    v1.x -= mean; v1.y -= mean; v1.z -= mean; v1.w -= mean;
    float s2 = v0.x*v0.x + v0.y*v0.y + v0.z*v0.z + v0.w*v0.w
             + v1.x*v1.x + v1.y*v1.y + v1.z*v1.z + v1.w*v1.w;
    #pragma unroll
    for (int o = 16; o; o >>= 1) s2 += __shfl_xor_sync(0xffffffffu, s2, o);
    float inv = rsqrtf(s2 * (1.0f / cD) + 1e-5f);
    const float4* g4 = (const float4*)gg;
    const float4* b4 = (const float4*)bt;
    float4 ga = g4[lane * 2], gb = g4[lane * 2 + 1];
    float4 ba = b4[lane * 2], bb = b4[lane * 2 + 1];
    float4 o0, o1;
    o0.x = v0.x * inv * ga.x + ba.x; o0.y = v0.y * inv * ga.y + ba.y;
    o0.z = v0.z * inv * ga.z + ba.z; o0.w = v0.w * inv * ga.w + ba.w;
    o1.x = v1.x * inv * gb.x + bb.x; o1.y = v1.y * inv * gb.y + bb.y;
    o1.z = v1.z * inv * gb.z + bb.z; o1.w = v1.w * inv * gb.w + bb.w;
    if (outf) {
        float4* po = (float4*)(outf + r * cD);
        po[lane * 2] = o0; po[lane * 2 + 1] = o1;
    }
    if (outb) {
        uint4 pk;
        pk.x = bf2u(o0.x, o0.y);
        pk.y = bf2u(o0.z, o0.w);
        pk.z = bf2u(o1.x, o1.y);
        pk.w = bf2u(o1.z, o1.w);
        ((uint4*)(outb + r * cD))[lane] = pk;
    }
    if (xeb) {
        const float4* e4 = (const float4*)(emb + r * cD);
        float4 e0 = e4[lane * 2], e1 = e4[lane * 2 + 1];
        uint4 pk;
        pk.x = bf2u(o0.x + e0.x, o0.y + e0.y);
        pk.y = bf2u(o0.z + e0.z, o0.w + e0.w);
        pk.z = bf2u(o1.x + e1.x, o1.y + e1.y);
        pk.w = bf2u(o1.z + e1.z, o1.w + e1.w);
        ((uint4*)(xeb + r * cD))[lane] = pk;
    }
}

// ---------------- bf16 tensor-core GEMM, 128x64x32, 3-stage cp.async ----------
// C[M,N] = A[M,K] * B^T (+bias). A [M,K] bf16 row-major, B [N,K] bf16 row-major.
// EPI: 0: Cf = v            (HN)
//      2: Cb = gelu(v+bias) (Y1)
//      3: Cf += ls*(v+bias), opt dual store D2 (attn_out, ffn2)
//      4: Cf = X + ls*(v+bias) (gat outs)
//      5: Cf = v; Cb = v    (EE)
//      6: Cb = v+bias       (QH, KH bf16)
// 256 threads, 8 warps (4M x 2N), warp tile 32x32, mma m16n8k16.
template <int EPI>
__global__ void __launch_bounds__(256, 3) k_mma(const __nv_bfloat16* __restrict__ A,
                                                const __nv_bfloat16* __restrict__ Bw,
                                                const float* __restrict__ bias,
                                                float* __restrict__ Cf,
                                                __nv_bfloat16* __restrict__ Cb,
                                                const float* __restrict__ X,
                                                const float* __restrict__ ls,
                                                float* __restrict__ D2,
                                                int M, int N, int K) {
    __shared__ __nv_bfloat16 As[3][128][40];
    __shared__ __nv_bfloat16 Bs[3][64][40];
    const int tid = threadIdx.x;
    const int m0 = blockIdx.y * 128, n0 = blockIdx.x * 64;
    const int wid = tid >> 5, lane = tid & 31;
    const int wm = (wid & 3) * 32, wn = (wid >> 2) * 32;
    const int g = lane >> 2, tg = lane & 3;
    float c[2][4][4] = {};

    auto loadA = [&](int st, int k0) {
        #pragma unroll
        for (int h = 0; h < 2; h++) {
            int idx = tid + h * 256;
            int row = idx >> 2, c4 = idx & 3;
            unsigned sa = (unsigned)__cvta_generic_to_shared(&As[st][row][c4 * 8]);
            cpasync16(sa, A + (size_t)(m0 + row) * K + k0 + c4 * 8);
        }
    };
    auto loadB = [&](int st, int k0) {
        int row = tid >> 2, c4 = tid & 3;
        unsigned sa = (unsigned)__cvta_generic_to_shared(&Bs[st][row][c4 * 8]);
        cpasync16(sa, Bw + (size_t)(n0 + row) * K + k0 + c4 * 8);
    };

    const int T = K >> 5;   // 32 k per iter
    loadA(0, 0); loadB(0, 0); cpcommit();
    if (T > 1) { loadA(1, 32); loadB(1, 32); cpcommit(); }
    for (int it = 0; it < T; it++) {
        int st = it % 3;
        if (it + 2 < T) {
            int nx = (it + 2) % 3;
            loadA(nx, (it + 2) * 32);
            loadB(nx, (it + 2) * 32);
            cpcommit();
            cpwait<2>();
        } else if (it + 1 < T) {
            cpwait<1>();
        } else {
            cpwait<0>();
        }
        __syncthreads();
        #pragma unroll
        for (int ks = 0; ks < 32; ks += 16) {
            unsigned a[2][4], b[4][2];
            #pragma unroll
            for (int i = 0; i < 2; i++) {
                int m = wm + i * 16 + g;
                a[i][0] = *(const unsigned*)&As[st][m][ks + 2 * tg];
                a[i][1] = *(const unsigned*)&As[st][m + 8][ks + 2 * tg];
                a[i][2] = *(const unsigned*)&As[st][m][ks + 2 * tg + 8];
                a[i][3] = *(const unsigned*)&As[st][m + 8][ks + 2 * tg + 8];
            }
            #pragma unroll
            for (int j = 0; j < 4; j++) {
                int n = wn + j * 8 + g;
                b[j][0] = *(const unsigned*)&Bs[st][n][ks + 2 * tg];
                b[j][1] = *(const unsigned*)&Bs[st][n][ks + 2 * tg + 8];
            }
            #pragma unroll
            for (int i = 0; i < 2; i++)
                #pragma unroll
                for (int j = 0; j < 4; j++)
                    mma16(c[i][j], a[i], b[j]);
        }
        __syncthreads();
    }
    #pragma unroll
    for (int i = 0; i < 2; i++) {
        #pragma unroll
        for (int j = 0; j < 4; j++) {
            int col = n0 + wn + j * 8 + tg * 2;
            #pragma unroll
            for (int p = 0; p < 4; p++) {
                int row = m0 + wm + i * 16 + g + ((p >= 2) ? 8 : 0);
                int cc = col + (p & 1);
                float v = c[i][j][p];
                if (EPI == 2 || EPI == 3 || EPI == 4 || EPI == 6) v += bias[cc];
                size_t idx = (size_t)row * N + cc;
                if (EPI == 0) {
                    Cf[idx] = v;
                } else if (EPI == 2) {
                    float gv = 0.5f * v * (1.0f + erff(v * 0.70710678118654752f));
                    Cb[idx] = __float2bfloat16(gv);
                } else if (EPI == 3) {
                    float nv = Cf[idx] + ls[cc] * v;
                    Cf[idx] = nv;
                    if (D2) D2[idx] = nv;
                } else if (EPI == 4) {
                    Cf[idx] = X[idx] + ls[cc] * v;
                } else if (EPI == 5) {
                    Cf[idx] = v;
                    Cb[idx] = __float2bfloat16(v);
                } else if (EPI == 6) {
                    Cb[idx] = __float2bfloat16(v);
                }
            }
        }
    }
}

// ---------------- flash attention, tensor-core (bf16 QK/PV, f32 softmax) ---------
// grid (NH, B, SPLITS), 192 threads = 6 warps, warp w owns queries w*16..w*16+15.
// K|V packed bf16 rows of 512: K at h*32, V at 256+h*32.
__global__ void __launch_bounds__(192) k_attn_flash() {
    __shared__ __nv_bfloat16 Qs[96][40];
    __shared__ __nv_bfloat16 Ks[64][40];
    __shared__ __nv_bfloat16 Vt[32][72];
    int h = blockIdx.x, b = blockIdx.y, s = blockIdx.z;
    int tid = threadIdx.x, w = tid >> 5, lane = tid & 31;
    int g = lane >> 2, tg = lane & 3;
    const __nv_bfloat16* khv = g_bf + B_KH;

    // stage Q (pre-scaled)
    for (int idx = tid; idx < 96 * 32; idx += 192) {
        int t = idx >> 5, d = idx & 31;
        int r = row_of(b, t);
        float qv = __bfloat162float(g_bf[B_QH + (size_t)r * cD + h * cDH + d]) * ATTN_SCALE;
        Qs[t][d] = __float2bfloat16(qv);
    }
    __syncthreads();

    // Q a-frags (2 k-steps)
    unsigned qa[2][4];
    int t0 = w * 16 + g;
    #pragma unroll
    for (int ks = 0; ks < 2; ks++) {
        qa[ks][0] = *(const unsigned*)&Qs[t0][ks * 16 + 2 * tg];
        qa[ks][1] = *(const unsigned*)&Qs[t0 + 8][ks * 16 + 2 * tg];
        qa[ks][2] = *(const unsigned*)&Qs[t0][ks * 16 + 2 * tg + 8];
        qa[ks][3] = *(const unsigned*)&Qs[t0 + 8][ks * 16 + 2 * tg + 8];
    }
    const float* br0 = g_buf + O_BIAS + (size_t)row_of(b, t0) * cHW;
    const float* br1 = g_buf + O_BIAS + (size_t)row_of(b, t0 + 8) * cHW;

    float m0 = -INFINITY, m1 = -INFINITY, d0 = 0.f, d1 = 0.f;
    float o[4][4] = {};

    for (int kt = 0; kt < 5; kt++) {
        int kbase = s * AKSPLIT + kt * 64;
        __syncthreads();
        // K tile [64 keys][32 dims]
        for (int idx = tid; idx < 256; idx += 192) {
            int kk = idx >> 2, c4 = idx & 3;
            *(uint4*)&Ks[kk][c4 * 8] =
                *(const uint4*)(khv + (size_t)(b * cHW + kbase + kk) * 512 + h * 32 + c4 * 8);
        }
        // V transposed [32 dims][64 keys]
        for (int idx = tid; idx < 64 * 16; idx += 192) {
            int kk = idx >> 4, dp = idx & 15;
            __nv_bfloat162 v2 = *(const __nv_bfloat162*)
                (khv + (size_t)(b * cHW + kbase + kk) * 512 + 256 + h * 32 + dp * 2);
            Vt[dp * 2][kk] = v2.x;
            Vt[dp * 2 + 1][kk] = v2.y;
        }
        __syncthreads();

        // S = Q K^T  (8 n-tiles of 8 keys)
        float sc[8][4] = {};
        #pragma unroll
        for (int j = 0; j < 8; j++) {
            #pragma unroll
            for (int ks = 0; ks < 2; ks++) {
                unsigned bb[2];
                bb[0] = *(const unsigned*)&Ks[j * 8 + g][ks * 16 + 2 * tg];
                bb[1] = *(const unsigned*)&Ks[j * 8 + g][ks * 16 + 2 * tg + 8];
                mma16(sc[j], qa[ks], bb);
            }
        }
        // bias + tile max
        float tm0 = -INFINITY, tm1 = -INFINITY;
        #pragma unroll
        for (int j = 0; j < 8; j++) {
            float2 bb0 = *(const float2*)(br0 + kbase + j * 8 + 2 * tg);
            float2 bb1 = *(const float2*)(br1 + kbase + j * 8 + 2 * tg);
            sc[j][0] += bb0.x; sc[j][1] += bb0.y;
            sc[j][2] += bb1.x; sc[j][3] += bb1.y;
            tm0 = fmaxf(tm0, fmaxf(sc[j][0], sc[j][1]));
            tm1 = fmaxf(tm1, fmaxf(sc[j][2], sc[j][3]));
        }
        tm0 = fmaxf(tm0, __shfl_xor_sync(0xffffffffu, tm0, 1));
        tm0 = fmaxf(tm0, __shfl_xor_sync(0xffffffffu, tm0, 2));
        tm1 = fmaxf(tm1, __shfl_xor_sync(0xffffffffu, tm1, 1));
        tm1 = fmaxf(tm1, __shfl_xor_sync(0xffffffffu, tm1, 2));
        float nm0 = fmaxf(m0, tm0), nm1 = fmaxf(m1, tm1);
        float c0 = __expf(m0 - nm0), c1 = __expf(m1 - nm1);
        m0 = nm0; m1 = nm1;
        // p, den, pack P as A-frags
        float ds0 = 0.f, ds1 = 0.f;
        unsigned pa[4][4];
        #pragma unroll
        for (int j = 0; j < 8; j++) {
            float p0 = __expf(sc[j][0] - m0);
            float p1 = __expf(sc[j][1] - m0);
            float p2 = __expf(sc[j][2] - m1);
            float p3 = __expf(sc[j][3] - m1);
            ds0 += p0 + p1; ds1 += p2 + p3;
            int kv = j >> 1;
            if ((j & 1) == 0) {
                pa[kv][0] = bf2u(p0, p1);
                pa[kv][1] = bf2u(p2, p3);
            } else {
                pa[kv][2] = bf2u(p0, p1);
                pa[kv][3] = bf2u(p2, p3);
            }
        }
        ds0 += __shfl_xor_sync(0xffffffffu, ds0, 1);
        ds0 += __shfl_xor_sync(0xffffffffu, ds0, 2);
        ds1 += __shfl_xor_sync(0xffffffffu, ds1, 1);
        ds1 += __shfl_xor_sync(0xffffffffu, ds1, 2);
        d0 = d0 * c0 + ds0;
        d1 = d1 * c1 + ds1;
        // rescale O, then O += P V
        #pragma unroll
        for (int jj = 0; jj < 4; jj++) {
            o[jj][0] *= c0; o[jj][1] *= c0;
            o[jj][2] *= c1; o[jj][3] *= c1;
        }
        #pragma unroll
        for (int jj = 0; jj < 4; jj++) {
            #pragma unroll
            for (int kv = 0; kv < 4; kv++) {
                unsigned bb[2];
                bb[0] = *(const unsigned*)&Vt[jj * 8 + g][kv * 16 + 2 * tg];
                bb[1] = *(const unsigned*)&Vt[jj * 8 + g][kv * 16 + 2 * tg + 8];
                mma16(o[jj], pa[kv], bb);
            }
        }
    }
    // write partials
    int base0 = ((b * cNH + h) * cTB + t0) * SPLITS + s;
    int base1 = ((b * cNH + h) * cTB + t0 + 8) * SPLITS + s;
    if (tg == 0) {
        g_buf[O_PM + base0] = m0; g_buf[O_PDEN + base0] = d0;
        g_buf[O_PM + base1] = m1; g_buf[O_PDEN + base1] = d1;
    }
    #pragma unroll
    for (int jj = 0; jj < 4; jj++) {
        int col = jj * 8 + 2 * tg;
        g_buf[O_PACC + (size_t)base0 * cDH + col]     = o[jj][0];
        g_buf[O_PACC + (size_t)base0 * cDH + col + 1] = o[jj][1];
        g_buf[O_PACC + (size_t)base1 * cDH + col]     = o[jj][2];
        g_buf[O_PACC + (size_t)base1 * cDH + col + 1] = o[jj][3];
    }
}

// merge -> AO bf16
__global__ void k_attn_merge() {
    int q = blockIdx.x, b = blockIdx.y;
    int t = threadIdx.x;
    int h = t >> 5, d = t & 31;
    int base = ((b * cNH + h) * cTB + q) * SPLITS;
    float M = -INFINITY;
    #pragma unroll
    for (int s = 0; s < SPLITS; s++) M = fmaxf(M, g_buf[O_PM + base + s]);
    float den = 0.f, a = 0.f;
    #pragma unroll
    for (int s = 0; s < SPLITS; s++) {
        float w = __expf(g_buf[O_PM + base + s] - M);
        den += g_buf[O_PDEN + base + s] * w;
        a += g_buf[O_PACC + (size_t)(base + s) * cDH + d] * w;
    }
    int r = row_of(b, q);
    g_bf[B_AO + (size_t)r * cD + t] = __float2bfloat16(a / den);
}

// ---------------- GAT kernels (CSR, no atomics) ----------------
__global__ void __launch_bounds__(256) k_gat_scores(const float* __restrict__ asrc,
                                                    const float* __restrict__ adst,
                                                    const float* __restrict__ aedge) {
    int warp = threadIdx.x >> 5, lane = threadIdx.x & 31;
    int r = blockIdx.x * 8 + warp;
    int h = lane >> 2, qq = lane & 3;
    int off = h * cDH + qq * 8;
    if (r < cTn) {
        const float4* xp = (const float4*)(g_buf + O_HN + (size_t)r * cD + off);
        float4 x0 = xp[0], x1 = xp[1];
        const float4* sp = (const float4*)(asrc + off);
        const float4* dp = (const float4*)(adst + off);
        float4 s0 = sp[0], s1 = sp[1], d0 = dp[0], d1 = dp[1];
        float ss = x0.x*s0.x + x0.y*s0.y + x0.z*s0.z + x0.w*s0.w
                 + x1.x*s1.x + x1.y*s1.y + x1.z*s1.z + x1.w*s1.w;
        float sd = x0.x*d0.x + x0.y*d0.y + x0.z*d0.z + x0.w*d0.w
                 + x1.x*d1.x + x1.y*d1.y + x1.z*d1.z + x1.w*d1.w;
        ss += __shfl_xor_sync(0xffffffffu, ss, 1);
        ss += __shfl_xor_sync(0xffffffffu, ss, 2);
        sd += __shfl_xor_sync(0xffffffffu, sd, 1);
        sd += __shfl_xor_sync(0xffffffffu, sd, 2);
        if (qq == 0) {
            g_As[r * cNH + h] = ss;
            g_Ad[r * cNH + h] = sd;
        }
    } else {
        int e = r - cTn;
        const float4* xp = (const float4*)(g_buf + O_EE + (size_t)e * cD + off);
        float4 x0 = xp[0], x1 = xp[1];
        const float4* ap = (const float4*)(aedge + off);
        float4 a0 = ap[0], a1 = ap[1];
        float se = x0.x*a0.x + x0.y*a0.y + x0.z*a0.z + x0.w*a0.w
                 + x1.x*a1.x + x1.y*a1.y + x1.z*a1.z + x1.w*a1.w;
        se += __shfl_xor_sync(0xffffffffu, se, 1);
        se += __shfl_xor_sync(0xffffffffu, se, 2);
        if (qq == 0) g_Ae[e * cNH + h] = se;
    }
}

// warp per dst node -> NAGG bf16
__global__ void __launch_bounds__(128) k_gat_node() {
    __shared__ float lg_s[4][64 * 8];
    __shared__ float md_s[4][16];
    int warp = threadIdx.x >> 5, lane = threadIdx.x & 31;
    int i = blockIdx.x * 4 + warp;
    int cnt = g_cnt[i];
    const float* hn = g_buf + O_HN;
    const float* ee = g_buf + O_EE;
    if (lane < 8) {
        float m = -INFINITY;
        for (int j = 0; j < cnt; j++) {
            int e = g_list[i * 64 + j];
            int s = g_src[e];
            float lg = g_As[s * cNH + lane] + g_Ad[i * cNH + lane] + g_Ae[e * cNH + lane];
            lg = (lg > 0.f) ? lg : 0.2f * lg;
            lg_s[warp][j * 8 + lane] = lg;
            m = fmaxf(m, lg);
        }
        float den = 0.f;
        for (int j = 0; j < cnt; j++) den += __expf(lg_s[warp][j * 8 + lane] - m);
        md_s[warp][lane] = m;
        md_s[warp][8 + lane] = den + 1e-9f;
    }
    __syncwarp();
    int hh = lane >> 2;
    float m = md_s[warp][hh];
    float dn = md_s[warp][8 + hh];
    float4 a0 = {0, 0, 0, 0}, a1 = {0, 0, 0, 0};
    for (int j = 0; j < cnt; j++) {
        int e = g_list[i * 64 + j];
        int s = g_src[e];
        float alpha = __expf(lg_s[warp][j * 8 + hh] - m) / dn;
        const float4* hp = (const float4*)(hn + (size_t)s * cD + lane * 8);
        const float4* ep = (const float4*)(ee + (size_t)e * cD + lane * 8);
        float4 h0 = hp[0], h1 = hp[1], e0 = ep[0], e1 = ep[1];
        a0.x += alpha * (h0.x + e0.x); a0.y += alpha * (h0.y + e0.y);
        a0.z += alpha * (h0.z + e0.z); a0.w += alpha * (h0.w + e0.w);
        a1.x += alpha * (h1.x + e1.x); a1.y += alpha * (h1.y + e1.y);
        a1.z += alpha * (h1.z + e1.z); a1.w += alpha * (h1.w + e1.w);
    }
    uint4 pk;
    pk.x = bf2u(a0.x, a0.y);
    pk.y = bf2u(a0.z, a0.w);
    pk.z = bf2u(a1.x, a1.y);
    pk.w = bf2u(a1.z, a1.w);
    ((uint4*)(g_bf + B_NAGG + (size_t)i * cD + lane * 8))[0] = pk;
}

// ---------------- host orchestration ----------------
extern "C" void kernel_launch(void* const* d_in, const int* in_sizes, int n_in,
                              void* d_out, int out_size) {
    const float* features   = (const float*)d_in[0];
    const float* boxes      = (const float*)d_in[1];
    const int*   edge_local = (const int*)  d_in[2];
    const float* nodes0     = (const float*)d_in[3];
    const float* edges0     = (const float*)d_in[4];
    const float* ln1_g      = (const float*)d_in[5];
    const float* ln1_b      = (const float*)d_in[6];
    const float* attn_in_w  = (const float*)d_in[7];
    const float* attn_in_b  = (const float*)d_in[8];
    const float* attn_out_w = (const float*)d_in[9];
    const float* attn_out_b = (const float*)d_in[10];
    const float* ls1        = (const float*)d_in[11];
    const float* ln2_g      = (const float*)d_in[12];
    const float* ln2_b      = (const float*)d_in[13];
    const float* gat_wn     = (const float*)d_in[14];
    const float* gat_we     = (const float*)d_in[15];
    const float* gat_a_src  = (const float*)d_in[16];
    const float* gat_a_dst  = (const float*)d_in[17];
    const float* gat_a_edge = (const float*)d_in[18];
    const float* gat_wo     = (const float*)d_in[19];
    const float* gat_bo     = (const float*)d_in[20];
    const float* gat_woe    = (const float*)d_in[21];
    const float* gat_boe    = (const float*)d_in[22];
    const float* ls2        = (const float*)d_in[23];
    const float* ln3_g      = (const float*)d_in[24];
    const float* ln3_b      = (const float*)d_in[25];
    const float* ffn_w1     = (const float*)d_in[26];
    const float* ffn_b1     = (const float*)d_in[27];
    const float* ffn_w2     = (const float*)d_in[28];
    const float* ffn_b2     = (const float*)d_in[29];
    const float* ls3        = (const float*)d_in[30];

    float* buf = nullptr;
    cudaGetSymbolAddress((void**)&buf, g_buf);
    __nv_bfloat16* bf = nullptr;
    cudaGetSymbolAddress((void**)&bf, g_bf);
    float* out = (float*)d_out;

    const int nTD = cT * cD;

    // -------- precompute --------
    k_edges<<<(cTe + 255) / 256, 256>>>(edge_local);
    k_csr<<<(cTe + 255) / 256, 256>>>();
    k_cvt<<<(cFKV * cD / 4 + 255) / 256, 256>>>(features, bf + B_FEAT, cFKV * cD / 4);
    k_cvt<<<(cL * 768 * cD / 4 + 255) / 256, 256>>>(attn_in_w, bf + B_WQKV,
                                                    cL * 768 * cD / 4);
    k_cvt<<<(cL * cD * cD / 4 + 255) / 256, 256>>>(attn_out_w, bf + B_WAO,
                                                   cL * cD * cD / 4);
    k_mma<6><<<dim3(512 / 64, cFKV / 128), 256>>>(                      // KV l=0 (bf16 out)
        bf + B_FEAT, bf + B_WQKV + cD * cD, attn_in_b + cD,
        nullptr, bf + B_KH, nullptr, nullptr, nullptr, cFKV, 512, cD);
    dim3 tb(32, 8);
    k_cvt_t<<<dim3(8, 8, cL), tb>>>(gat_wn, bf + B_WGN, cD, cD);
    k_cvt_t<<<dim3(8, 8, cL), tb>>>(gat_we, bf + B_WGE, cD, cD);
    k_cvt_t<<<dim3(8, 8, cL), tb>>>(gat_wo, bf + B_WGO, cD, cD);
    k_cvt_t<<<dim3(8, 8, cL), tb>>>(gat_woe, bf + B_WGOE, cD, cD);
    k_cvt_t<<<dim3(32, 8, cL), tb>>>(ffn_w1, bf + B_WF1, cD, cFF);
    k_cvt_t<<<dim3(8, 32, cL), tb>>>(ffn_w2, bf + B_WF2, cFF, cD);
    k_node_heat<<<cTn, 256>>>(boxes);
    k_edge_heat<<<cTe, 256>>>(boxes);
    k_emb<<<nTD / 256, 256>>>(boxes, nodes0, edges0);

    for (int l = 0; l < cL; l++) {
        const __nv_bfloat16* WQ = bf + B_WQKV + (size_t)l * 768 * cD;
        const float* bqkv = attn_in_b + (size_t)l * 3 * cD;

        // ---- cross attention ----
        k_ln<<<cT / 8, 256>>>(buf + O_Q, ln1_g + l * cD, ln1_b + l * cD,
                              nullptr, bf + B_X, nullptr, nullptr);
        k_mma<6><<<dim3(cD / 64, cT / 128), 256>>>(
            bf + B_X, WQ, bqkv, nullptr, bf + B_QH, nullptr, nullptr, nullptr,
            cT, cD, cD);
        if (l > 0) {
            k_mma<6><<<dim3(512 / 64, cFKV / 128), 256>>>(
                bf + B_FEAT, WQ + cD * cD, bqkv + cD, nullptr, bf + B_KH,
                nullptr, nullptr, nullptr, cFKV, 512, cD);
        }
        k_attn_flash<<<dim3(cNH, cB, SPLITS), 192>>>();
        k_attn_merge<<<dim3(cTB, cB), 256>>>();
        // attn_out fused residual: Q += ls1 * (AO @ W^T + b)
        k_mma<3><<<dim3(cD / 64, cT / 128), 256>>>(
            bf + B_AO, bf + B_WAO + (size_t)l * cD * cD, attn_out_b + l * cD,
            buf + O_Q, nullptr, nullptr, ls1 + l * cD, nullptr, cT, cD, cD);

        // ---- GAT ----
        k_ln<<<cT / 8, 256>>>(buf + O_Q, ln2_g + l * cD, ln2_b + l * cD,
                              buf + O_X, nullptr, bf + B_XE, buf + O_EMB);
        k_mma<0><<<dim3(cD / 64, cTn / 128), 256>>>(
            bf + B_XE, bf + B_WGN + (size_t)l * cD * cD, nullptr, buf + O_HN,
            nullptr, nullptr, nullptr, nullptr, cTn, cD, cD);
        k_mma<5><<<dim3(cD / 64, cTe / 128), 256>>>(
            bf + B_XE + (size_t)cTn * cD, bf + B_WGE + (size_t)l * cD * cD, nullptr,
            buf + O_EE, bf + B_EE, nullptr, nullptr, nullptr, cTe, cD, cD);
        k_gat_scores<<<cT / 8, 256>>>(gat_a_src + l * cD, gat_a_dst + l * cD,
                                      gat_a_edge + l * cD);
        k_gat_node<<<cTn / 4, 128>>>();
        k_mma<4><<<dim3(cD / 64, cTn / 128), 256>>>(
            bf + B_NAGG, bf + B_WGO + (size_t)l * cD * cD, gat_bo + l * cD,
            buf + O_Q, nullptr, buf + O_X, ls2 + l * cD, nullptr, cTn, cD, cD);
        k_mma<4><<<dim3(cD / 64, cTe / 128), 256>>>(
            bf + B_EE, bf + B_WGOE + (size_t)l * cD * cD, gat_boe + l * cD,
            buf + O_Q + (size_t)cTn * cD, nullptr, buf + O_X + (size_t)cTn * cD,
            ls2 + l * cD, nullptr, cTe, cD, cD);

        // ---- FFN ----
        k_ln<<<cT / 8, 256>>>(buf + O_Q, ln3_g + l * cD, ln3_b + l * cD,
                              nullptr, bf + B_X, nullptr, nullptr);
        k_mma<2><<<dim3(cFF / 64, cT / 128), 256>>>(
            bf + B_X, bf + B_WF1 + (size_t)l * cFF * cD, ffn_b1 + l * cFF,
            nullptr, bf + B_Y1, nullptr, nullptr, nullptr, cT, cFF, cD);
        k_mma<3><<<dim3(cD / 64, cT / 128), 256>>>(
            bf + B_Y1, bf + B_WF2 + (size_t)l * cD * cFF, ffn_b2 + l * cD,
            buf + O_Q, nullptr, nullptr, ls3 + l * cD, out + (size_t)l * nTD,
            cT, cD, cFF);
    }
    (void)in_sizes; (void)n_in; (void)out_size;
}